// round 1
// baseline (speedup 1.0000x reference)
#include <cuda_runtime.h>
#include <math.h>

// Problem constants
#define LQ    2048      // query length
#define BATCH 2
#define EMB   1024
#define NH    16
#define HD    64        // head dim
#define SK    2048      // key length
#define BHn   32        // BATCH*NH
#define MR    4096      // LQ*BATCH (GEMM rows)

// ---------------- scratch (device globals, no allocs) ----------------
__device__ float g_q[BHn * LQ * HD];             // 16 MB, [bh][l][d], pre-scaled by 1/8
__device__ float g_k[BHn * SK * HD];             // 16 MB
__device__ float g_v[BHn * SK * HD];             // 16 MB
__device__ float g_attn[BHn * LQ * SK];          // 512 MB, sigmoid scores
__device__ float g_den[BHn * LQ];                // row sums
__device__ float g_ctx[MR * EMB];                // 16 MB, attention output in (L,B,E) GEMM layout

// =====================================================================
// in-projection: C[r][n] = X[r][:] . W[n][:] + b[n]; scatter to per-head
// layout. blockIdx.z selects q/k/v. 128x128 tile, BK=8, 8x8 microtile.
// =====================================================================
__global__ __launch_bounds__(256) void k_inproj(
    const float* __restrict__ qin, const float* __restrict__ kin,
    const float* __restrict__ vin, const float* __restrict__ W,
    const float* __restrict__ bias)
{
    __shared__ float As[8][128];
    __shared__ float Bs[8][128];

    const int p = blockIdx.z;
    const float* X  = (p == 0) ? qin : (p == 1) ? kin : vin;
    const float* Wp = W + (size_t)p * EMB * EMB;
    const float* bp = bias + p * EMB;
    float* Out = (p == 0) ? g_q : (p == 1) ? g_k : g_v;
    const float scale = (p == 0) ? 0.125f : 1.0f;   // 1/sqrt(64) for q

    const int tid = threadIdx.x;
    const int tx = tid & 15, ty = tid >> 4;
    const int m0 = blockIdx.y * 128, n0 = blockIdx.x * 128;
    const int lr = tid >> 1;            // 0..127
    const int lc = (tid & 1) * 4;       // 0 or 4

    float acc[8][8];
#pragma unroll
    for (int i = 0; i < 8; i++)
#pragma unroll
        for (int j = 0; j < 8; j++) acc[i][j] = 0.0f;

    for (int k0 = 0; k0 < EMB; k0 += 8) {
        float4 av = *(const float4*)(X  + (size_t)(m0 + lr) * EMB + k0 + lc);
        float4 bv = *(const float4*)(Wp + (size_t)(n0 + lr) * EMB + k0 + lc);
        __syncthreads();
        As[lc + 0][lr] = av.x; As[lc + 1][lr] = av.y;
        As[lc + 2][lr] = av.z; As[lc + 3][lr] = av.w;
        Bs[lc + 0][lr] = bv.x; Bs[lc + 1][lr] = bv.y;
        Bs[lc + 2][lr] = bv.z; Bs[lc + 3][lr] = bv.w;
        __syncthreads();
#pragma unroll
        for (int k = 0; k < 8; k++) {
            float a[8], b[8];
            *(float4*)(a)     = *(const float4*)&As[k][ty * 8];
            *(float4*)(a + 4) = *(const float4*)&As[k][ty * 8 + 4];
            *(float4*)(b)     = *(const float4*)&Bs[k][tx * 8];
            *(float4*)(b + 4) = *(const float4*)&Bs[k][tx * 8 + 4];
#pragma unroll
            for (int i = 0; i < 8; i++)
#pragma unroll
                for (int j = 0; j < 8; j++)
                    acc[i][j] = fmaf(a[i], b[j], acc[i][j]);
        }
    }

#pragma unroll
    for (int i = 0; i < 8; i++) {
        const int r = m0 + ty * 8 + i;
        const int l = r >> 1, bb = r & 1;       // r = l*BATCH + b
#pragma unroll
        for (int j = 0; j < 8; j++) {
            const int n = n0 + tx * 8 + j;
            const float c = (acc[i][j] + bp[n]) * scale;
            const int h = n >> 6, d = n & 63;
            Out[((size_t)(bb * NH + h) * LQ + l) * HD + d] = c;
        }
    }
}

// =====================================================================
// zero denominators
// =====================================================================
__global__ void k_zero_den()
{
    int i = blockIdx.x * 256 + threadIdx.x;
    if (i < BHn * LQ) g_den[i] = 0.0f;
}

// =====================================================================
// scores: attn[bh][l][s] = sigmoid(q[bh][l][:] . k[bh][s][:]); row sums
// into g_den via one atomicAdd per (row, CTA). 128x128 tile, K=64.
// =====================================================================
__global__ __launch_bounds__(256) void k_scores()
{
    __shared__ float Qs[8][128];
    __shared__ float Ks[8][128];

    const int bh = blockIdx.z;
    const int l0 = blockIdx.y * 128, s0 = blockIdx.x * 128;
    const float* Q  = g_q + (size_t)bh * LQ * HD;
    const float* Kp = g_k + (size_t)bh * SK * HD;

    const int tid = threadIdx.x;
    const int tx = tid & 15, ty = tid >> 4;
    const int lr = tid >> 1;
    const int lc = (tid & 1) * 4;

    float acc[8][8];
#pragma unroll
    for (int i = 0; i < 8; i++)
#pragma unroll
        for (int j = 0; j < 8; j++) acc[i][j] = 0.0f;

#pragma unroll
    for (int k0 = 0; k0 < HD; k0 += 8) {
        float4 av = *(const float4*)(Q  + (size_t)(l0 + lr) * HD + k0 + lc);
        float4 bv = *(const float4*)(Kp + (size_t)(s0 + lr) * HD + k0 + lc);
        __syncthreads();
        Qs[lc + 0][lr] = av.x; Qs[lc + 1][lr] = av.y;
        Qs[lc + 2][lr] = av.z; Qs[lc + 3][lr] = av.w;
        Ks[lc + 0][lr] = bv.x; Ks[lc + 1][lr] = bv.y;
        Ks[lc + 2][lr] = bv.z; Ks[lc + 3][lr] = bv.w;
        __syncthreads();
#pragma unroll
        for (int k = 0; k < 8; k++) {
            float a[8], b[8];
            *(float4*)(a)     = *(const float4*)&Qs[k][ty * 8];
            *(float4*)(a + 4) = *(const float4*)&Qs[k][ty * 8 + 4];
            *(float4*)(b)     = *(const float4*)&Ks[k][tx * 8];
            *(float4*)(b + 4) = *(const float4*)&Ks[k][tx * 8 + 4];
#pragma unroll
            for (int i = 0; i < 8; i++)
#pragma unroll
                for (int j = 0; j < 8; j++)
                    acc[i][j] = fmaf(a[i], b[j], acc[i][j]);
        }
    }

    float* Arow = g_attn + (size_t)bh * LQ * SK;
    float rsum[8];
#pragma unroll
    for (int i = 0; i < 8; i++) {
        float r0 = 0.0f;
#pragma unroll
        for (int j = 0; j < 8; j++) {
            float sg = __fdividef(1.0f, 1.0f + __expf(-acc[i][j]));
            acc[i][j] = sg;
            r0 += sg;
        }
        rsum[i] = r0;
        const size_t off = (size_t)(l0 + ty * 8 + i) * SK + s0 + tx * 8;
        *(float4*)(Arow + off)     = make_float4(acc[i][0], acc[i][1], acc[i][2], acc[i][3]);
        *(float4*)(Arow + off + 4) = make_float4(acc[i][4], acc[i][5], acc[i][6], acc[i][7]);
    }

    // reduce row sums across the 16 tx lanes (width-16 segments)
#pragma unroll
    for (int off = 8; off > 0; off >>= 1)
#pragma unroll
        for (int i = 0; i < 8; i++)
            rsum[i] += __shfl_down_sync(0xffffffffu, rsum[i], off, 16);
    if (tx == 0) {
#pragma unroll
        for (int i = 0; i < 8; i++)
            atomicAdd(&g_den[bh * LQ + l0 + ty * 8 + i], rsum[i]);
    }
}

// =====================================================================
// avg_weights[b][l][s] = (1/H) * sum_h attn[b*H+h][l][s]
// =====================================================================
__global__ __launch_bounds__(256) void k_avg(float* __restrict__ outAvg)
{
    const size_t t = (size_t)blockIdx.x * 256 + threadIdx.x;
    const int s = (int)(t & (SK - 1));
    const int l = (int)((t >> 11) & (LQ - 1));
    const int b = (int)(t >> 22);
    float sum = 0.0f;
#pragma unroll
    for (int h = 0; h < NH; h++)
        sum += g_attn[((size_t)(b * NH + h) * LQ + l) * SK + s];
    outAvg[t] = sum * (1.0f / NH);
}

// =====================================================================
// PV: ctx[l][b][h*64+d] = (1/(den+1e-4)) * sum_s attn[bh][l][s] * v[bh][s][d]
// per head: GEMM 2048x64x2048. 128x64 tile, BK=16, 8x4 microtile.
// =====================================================================
__global__ __launch_bounds__(256) void k_pv()
{
    __shared__ float As[16][128];
    __shared__ float Vs[16][64];

    const int bh = blockIdx.z;
    const int l0 = blockIdx.y * 128;
    const float* Ap = g_attn + (size_t)bh * LQ * SK;
    const float* Vp = g_v   + (size_t)bh * SK * HD;

    const int tid = threadIdx.x;
    const int tx = tid & 15, ty = tid >> 4;
    const int lr = tid >> 1;            // A tile row 0..127
    const int lc = (tid & 1) * 8;       // A tile col 0 or 8
    const int vr = tid >> 4;            // V tile row 0..15
    const int vc = (tid & 15) * 4;      // V tile col

    float acc[8][4];
#pragma unroll
    for (int i = 0; i < 8; i++)
#pragma unroll
        for (int j = 0; j < 4; j++) acc[i][j] = 0.0f;

    for (int k0 = 0; k0 < SK; k0 += 16) {
        float4 a0 = *(const float4*)(Ap + (size_t)(l0 + lr) * SK + k0 + lc);
        float4 a1 = *(const float4*)(Ap + (size_t)(l0 + lr) * SK + k0 + lc + 4);
        float4 vv = *(const float4*)(Vp + (size_t)(k0 + vr) * HD + vc);
        __syncthreads();
        As[lc + 0][lr] = a0.x; As[lc + 1][lr] = a0.y;
        As[lc + 2][lr] = a0.z; As[lc + 3][lr] = a0.w;
        As[lc + 4][lr] = a1.x; As[lc + 5][lr] = a1.y;
        As[lc + 6][lr] = a1.z; As[lc + 7][lr] = a1.w;
        *(float4*)&Vs[vr][vc] = vv;
        __syncthreads();
#pragma unroll
        for (int k = 0; k < 16; k++) {
            float a[8], b[4];
            *(float4*)(a)     = *(const float4*)&As[k][ty * 8];
            *(float4*)(a + 4) = *(const float4*)&As[k][ty * 8 + 4];
            *(float4*)(b)     = *(const float4*)&Vs[k][tx * 4];
#pragma unroll
            for (int i = 0; i < 8; i++)
#pragma unroll
                for (int j = 0; j < 4; j++)
                    acc[i][j] = fmaf(a[i], b[j], acc[i][j]);
        }
    }

    const int b = bh >> 4, h = bh & 15;
#pragma unroll
    for (int i = 0; i < 8; i++) {
        const int l = l0 + ty * 8 + i;
        const float inv = __fdividef(1.0f, g_den[bh * LQ + l] + 1e-4f);
        float4 o = make_float4(acc[i][0] * inv, acc[i][1] * inv,
                               acc[i][2] * inv, acc[i][3] * inv);
        *(float4*)&g_ctx[(size_t)(l * BATCH + b) * EMB + h * HD + tx * 4] = o;
    }
}

// =====================================================================
// out-projection: out[r][n] = ctx[r][:] . Wo[n][:] + bo[n]
// =====================================================================
__global__ __launch_bounds__(256) void k_outproj(
    const float* __restrict__ Wo, const float* __restrict__ bo,
    float* __restrict__ out)
{
    __shared__ float As[8][128];
    __shared__ float Bs[8][128];

    const int tid = threadIdx.x;
    const int tx = tid & 15, ty = tid >> 4;
    const int m0 = blockIdx.y * 128, n0 = blockIdx.x * 128;
    const int lr = tid >> 1;
    const int lc = (tid & 1) * 4;

    float acc[8][8];
#pragma unroll
    for (int i = 0; i < 8; i++)
#pragma unroll
        for (int j = 0; j < 8; j++) acc[i][j] = 0.0f;

    for (int k0 = 0; k0 < EMB; k0 += 8) {
        float4 av = *(const float4*)(g_ctx + (size_t)(m0 + lr) * EMB + k0 + lc);
        float4 bv = *(const float4*)(Wo    + (size_t)(n0 + lr) * EMB + k0 + lc);
        __syncthreads();
        As[lc + 0][lr] = av.x; As[lc + 1][lr] = av.y;
        As[lc + 2][lr] = av.z; As[lc + 3][lr] = av.w;
        Bs[lc + 0][lr] = bv.x; Bs[lc + 1][lr] = bv.y;
        Bs[lc + 2][lr] = bv.z; Bs[lc + 3][lr] = bv.w;
        __syncthreads();
#pragma unroll
        for (int k = 0; k < 8; k++) {
            float a[8], b[8];
            *(float4*)(a)     = *(const float4*)&As[k][ty * 8];
            *(float4*)(a + 4) = *(const float4*)&As[k][ty * 8 + 4];
            *(float4*)(b)     = *(const float4*)&Bs[k][tx * 8];
            *(float4*)(b + 4) = *(const float4*)&Bs[k][tx * 8 + 4];
#pragma unroll
            for (int i = 0; i < 8; i++)
#pragma unroll
                for (int j = 0; j < 8; j++)
                    acc[i][j] = fmaf(a[i], b[j], acc[i][j]);
        }
    }

#pragma unroll
    for (int i = 0; i < 8; i++) {
        const int r = m0 + ty * 8 + i;
#pragma unroll
        for (int j = 0; j < 8; j += 4) {
            const int n = n0 + tx * 8 + j;
            float4 o = make_float4(acc[i][j + 0] + bo[n + 0],
                                   acc[i][j + 1] + bo[n + 1],
                                   acc[i][j + 2] + bo[n + 2],
                                   acc[i][j + 3] + bo[n + 3]);
            *(float4*)(out + (size_t)r * EMB + n) = o;
        }
    }
}

// =====================================================================
extern "C" void kernel_launch(void* const* d_in, const int* in_sizes, int n_in,
                              void* d_out, int out_size)
{
    (void)in_sizes; (void)n_in; (void)out_size;
    const float* q    = (const float*)d_in[0];
    const float* k    = (const float*)d_in[1];
    const float* v    = (const float*)d_in[2];
    const float* Wqkv = (const float*)d_in[3];
    const float* bqkv = (const float*)d_in[4];
    const float* Wo   = (const float*)d_in[5];
    const float* bo   = (const float*)d_in[6];
    float* out    = (float*)d_out;
    float* outAvg = out + (size_t)LQ * BATCH * EMB;   // avg_weights after out

    k_inproj<<<dim3(EMB / 128, MR / 128, 3), 256>>>(q, k, v, Wqkv, bqkv);
    k_zero_den<<<(BHn * LQ + 255) / 256, 256>>>();
    k_scores<<<dim3(SK / 128, LQ / 128, BHn), 256>>>();
    k_avg<<<(int)(((size_t)BATCH * LQ * SK) / 256), 256>>>(outAvg);
    k_pv<<<dim3(1, LQ / 128, BHn), 256>>>();
    k_outproj<<<dim3(EMB / 128, MR / 128), 256>>>(Wo, bo, out);
}

// round 2
// speedup vs baseline: 2.1477x; 2.1477x over previous
#include <cuda_runtime.h>
#include <math.h>
#include <stdint.h>

// Problem constants
#define LQ    2048
#define BATCH 2
#define EMB   1024
#define NH    16
#define HD    64
#define SK    2048
#define BHn   32
#define MR    4096

// ---------------- scratch (device globals) ----------------
__device__ float g_q[BHn * LQ * HD];               // [bh][l][d], pre-scaled by 1/8
__device__ float g_k[BHn * SK * HD];               // [bh][s][d]
__device__ float g_vt[BHn * HD * SK];              // [bh][d][s]  (V transposed)
__device__ float g_attn[(size_t)BHn * LQ * SK];    // 512 MB sigmoid scores
__device__ float g_ctx[MR * EMB];                  // attention out, (L,B,E) rows

// ---------------- tf32 MMA helpers ----------------
__device__ __forceinline__ uint32_t f2tf(float f) {
    uint32_t u;
    asm("cvt.rna.tf32.f32 %0, %1;" : "=r"(u) : "f"(f));
    return u;
}

#define LDSM4(R0,R1,R2,R3,ADDR) \
    asm volatile("ldmatrix.sync.aligned.m8n8.x4.shared.b16 {%0,%1,%2,%3}, [%4];" \
        : "=r"(R0), "=r"(R1), "=r"(R2), "=r"(R3) : "r"(ADDR))

#define MMA8(C,A,B0,B1) \
    asm volatile("mma.sync.aligned.m16n8k8.row.col.f32.tf32.tf32.f32 " \
        "{%0,%1,%2,%3},{%4,%5,%6,%7},{%8,%9},{%0,%1,%2,%3};" \
        : "+f"((C)[0]), "+f"((C)[1]), "+f"((C)[2]), "+f"((C)[3]) \
        : "r"((A)[0]), "r"((A)[1]), "r"((A)[2]), "r"((A)[3]), "r"(B0), "r"(B1))

// =====================================================================
// V1 core: CTA tile 128x128, BK=32, 256 threads (8 warps 2x4, warp 64x32)
// A: MxK row-major (k contig), B: NxK row-major (k contig) -> col-major op.
// Both M,N tiles = 128 rows staged K-contiguous with XOR-granule swizzle.
// acc[mt 0..3][nt 0..3][c0..c3] per thread.
// =====================================================================
__device__ __forceinline__ void gemm_v1(
    const float* __restrict__ Ag, int lda,
    const float* __restrict__ Bg, int ldb,
    int K, float (&acc)[4][4][4])
{
    __shared__ uint32_t As[128 * 32];
    __shared__ uint32_t Bs[128 * 32];

    const int tid  = threadIdx.x;
    const int lane = tid & 31, warp = tid >> 5;
    const int wm0 = (warp >> 2) * 64;
    const int wn0 = (warp & 3) * 32;

    // staging: row = tid/2 (0..127), granules (tid&1)*4 .. +3 (16 floats)
    const int srow = tid >> 1;
    const int sg0  = (tid & 1) * 4;
    const int swz  = srow & 7;
    const float* Ap = Ag + (size_t)srow * lda + sg0 * 4;
    const float* Bp = Bg + (size_t)srow * ldb + sg0 * 4;

    // ldmatrix per-thread addressing
    const int arow = wm0 + (lane & 15);
    const int agh  = lane >> 4;
    const int brow = wn0 + (lane & 7) + ((lane >> 4) << 3);
    const int bgh  = (lane >> 3) & 1;
    const int lswz = lane & 7;               // == arow&7 == brow&7
    const uint32_t as_b = (uint32_t)__cvta_generic_to_shared(As);
    const uint32_t bs_b = (uint32_t)__cvta_generic_to_shared(Bs);
    const uint32_t aBase = as_b + (uint32_t)arow * 128;
    const uint32_t bBase = bs_b + (uint32_t)brow * 128;

#pragma unroll
    for (int mt = 0; mt < 4; mt++)
#pragma unroll
        for (int nt = 0; nt < 4; nt++)
#pragma unroll
            for (int c = 0; c < 4; c++) acc[mt][nt][c] = 0.0f;

    float4 ra[4], rb[4];
#pragma unroll
    for (int i = 0; i < 4; i++) {
        ra[i] = *(const float4*)(Ap + i * 4);
        rb[i] = *(const float4*)(Bp + i * 4);
    }

    for (int k0 = 0; k0 < K; k0 += 32) {
        // store staged tile (convert to tf32)
#pragma unroll
        for (int i = 0; i < 4; i++) {
            const int g = sg0 + i;
            const int idx = srow * 32 + ((g ^ swz) << 2);
            uint4 ua = make_uint4(f2tf(ra[i].x), f2tf(ra[i].y), f2tf(ra[i].z), f2tf(ra[i].w));
            uint4 ub = make_uint4(f2tf(rb[i].x), f2tf(rb[i].y), f2tf(rb[i].z), f2tf(rb[i].w));
            *(uint4*)&As[idx] = ua;
            *(uint4*)&Bs[idx] = ub;
        }
        __syncthreads();

        if (k0 + 32 < K) {
            Ap += 32; Bp += 32;
#pragma unroll
            for (int i = 0; i < 4; i++) {
                ra[i] = *(const float4*)(Ap + i * 4);
                rb[i] = *(const float4*)(Bp + i * 4);
            }
        }

#pragma unroll
        for (int s = 0; s < 4; s++) {
            const uint32_t gA = (uint32_t)(((2 * s + agh) ^ lswz) << 4);
            const uint32_t gB = (uint32_t)(((2 * s + bgh) ^ lswz) << 4);
            uint32_t af[4][4], bf[4][2];
#pragma unroll
            for (int mt = 0; mt < 4; mt++)
                LDSM4(af[mt][0], af[mt][1], af[mt][2], af[mt][3],
                      aBase + (uint32_t)(mt * 2048) + gA);
            LDSM4(bf[0][0], bf[0][1], bf[1][0], bf[1][1], bBase + gB);
            LDSM4(bf[2][0], bf[2][1], bf[3][0], bf[3][1], bBase + 2048u + gB);
#pragma unroll
            for (int mt = 0; mt < 4; mt++)
#pragma unroll
                for (int nt = 0; nt < 4; nt++)
                    MMA8(acc[mt][nt], af[mt], bf[nt][0], bf[nt][1]);
        }
        __syncthreads();
    }
}

// =====================================================================
// in-projection (tf32): grid (8, 32, 3), 256 thr
// =====================================================================
__global__ __launch_bounds__(256, 1) void k_inproj_t(
    const float* __restrict__ qin, const float* __restrict__ kin,
    const float* __restrict__ vin, const float* __restrict__ W,
    const float* __restrict__ bias)
{
    const int p = blockIdx.z;
    const float* X  = (p == 0) ? qin : (p == 1) ? kin : vin;
    const float* Wp = W + (size_t)p * EMB * EMB;
    const float* bp = bias + p * EMB;
    const float scale = (p == 0) ? 0.125f : 1.0f;
    const int m0 = blockIdx.y * 128, n0 = blockIdx.x * 128;

    float acc[4][4][4];
    gemm_v1(X + (size_t)m0 * EMB, EMB, Wp + (size_t)n0 * EMB, EMB, EMB, acc);

    const int lane = threadIdx.x & 31, warp = threadIdx.x >> 5;
    const int wm0 = (warp >> 2) * 64, wn0 = (warp & 3) * 32;

#pragma unroll
    for (int nt = 0; nt < 4; nt++) {
        const int c = n0 + wn0 + nt * 8 + 2 * (lane & 3);
        const float b0 = bp[c], b1 = bp[c + 1];
        const int h = c >> 6, d = c & 63;
#pragma unroll
        for (int mt = 0; mt < 4; mt++) {
            const int r = m0 + wm0 + mt * 16 + (lane >> 2);
#pragma unroll
            for (int half = 0; half < 2; half++) {
                const int rr = r + half * 8;
                const float v0 = (acc[mt][nt][half * 2 + 0] + b0) * scale;
                const float v1 = (acc[mt][nt][half * 2 + 1] + b1) * scale;
                const int l = rr >> 1, bb = rr & 1;
                const int bh = bb * NH + h;
                if (p == 0)
                    *(float2*)&g_q[((size_t)bh * LQ + l) * HD + d] = make_float2(v0, v1);
                else if (p == 1)
                    *(float2*)&g_k[((size_t)bh * SK + l) * HD + d] = make_float2(v0, v1);
                else {
                    g_vt[((size_t)bh * HD + d)     * SK + l] = v0;
                    g_vt[((size_t)bh * HD + d + 1) * SK + l] = v1;
                }
            }
        }
    }
}

// =====================================================================
// scores (tf32): attn = sigmoid(q.kT). grid (16, 16, 32), 256 thr
// =====================================================================
__global__ __launch_bounds__(256, 1) void k_scores_t()
{
    const int bh = blockIdx.z;
    const int l0 = blockIdx.y * 128, s0 = blockIdx.x * 128;

    float acc[4][4][4];
    gemm_v1(g_q + ((size_t)bh * LQ + l0) * HD, HD,
            g_k + ((size_t)bh * SK + s0) * HD, HD, HD, acc);

    const int lane = threadIdx.x & 31, warp = threadIdx.x >> 5;
    const int wm0 = (warp >> 2) * 64, wn0 = (warp & 3) * 32;
    float* Arow = g_attn + (size_t)bh * LQ * SK;

#pragma unroll
    for (int mt = 0; mt < 4; mt++) {
        const int r = l0 + wm0 + mt * 16 + (lane >> 2);
#pragma unroll
        for (int nt = 0; nt < 4; nt++) {
            const int c = s0 + wn0 + nt * 8 + 2 * (lane & 3);
#pragma unroll
            for (int half = 0; half < 2; half++) {
                const int rr = r + half * 8;
                const float s0v = __fdividef(1.0f, 1.0f + __expf(-acc[mt][nt][half * 2 + 0]));
                const float s1v = __fdividef(1.0f, 1.0f + __expf(-acc[mt][nt][half * 2 + 1]));
                *(float2*)&Arow[(size_t)rr * SK + c] = make_float2(s0v, s1v);
            }
        }
    }
}

// =====================================================================
// avg_weights (float4 vectorized): grid 8192, 256 thr
// =====================================================================
__global__ __launch_bounds__(256) void k_avg(float* __restrict__ outAvg)
{
    const size_t t = (size_t)blockIdx.x * 256 + threadIdx.x;   // float4 index
    const int s4 = (int)(t & (SK / 4 - 1));
    const int l  = (int)((t >> 9) & (LQ - 1));
    const int b  = (int)(t >> 20);
    float4 sum = make_float4(0.f, 0.f, 0.f, 0.f);
#pragma unroll
    for (int h = 0; h < NH; h++) {
        const float4 v = *(const float4*)&g_attn[((size_t)(b * NH + h) * LQ + l) * SK + s4 * 4];
        sum.x += v.x; sum.y += v.y; sum.z += v.z; sum.w += v.w;
    }
    const float inv = 1.0f / NH;
    sum.x *= inv; sum.y *= inv; sum.z *= inv; sum.w *= inv;
    *(float4*)&outAvg[t * 4] = sum;
}

// =====================================================================
// PV (tf32): ctx = (attn/den) @ V. CTA 128x64, BK=32, 128 thr (4 warps 2x2,
// warp 64x32). Denominator accumulated during A staging (thread = attn row).
// grid (16, 32)
// =====================================================================
__global__ __launch_bounds__(128, 1) void k_pv_t()
{
    __shared__ uint32_t As[128 * 32];
    __shared__ uint32_t Bs[64 * 32];

    const int bh = blockIdx.y;
    const int l0 = blockIdx.x * 128;
    const int b = bh >> 4, h = bh & 15;
    const float* Ag = g_attn + ((size_t)bh * LQ + l0) * SK;
    const float* Bg = g_vt + (size_t)bh * HD * SK;

    const int tid = threadIdx.x, lane = tid & 31, warp = tid >> 5;
    const int wm0 = (warp >> 1) * 64, wn0 = (warp & 1) * 32;

    // staging: A row = tid (full row, 8 granules); B row = tid&63, 4 granules
    const int swzA = tid & 7;
    const int srB = tid & 63, sgB0 = (tid >> 6) * 4;
    const int swzB = srB & 7;
    const float* Ap = Ag + (size_t)tid * SK;
    const float* Bp = Bg + (size_t)srB * SK + sgB0 * 4;

    const int arow = wm0 + (lane & 15);
    const int agh  = lane >> 4;
    const int brow = wn0 + (lane & 7) + ((lane >> 4) << 3);
    const int bgh  = (lane >> 3) & 1;
    const int lswz = lane & 7;
    const uint32_t as_b = (uint32_t)__cvta_generic_to_shared(As);
    const uint32_t bs_b = (uint32_t)__cvta_generic_to_shared(Bs);
    const uint32_t aBase = as_b + (uint32_t)arow * 128;
    const uint32_t bBase = bs_b + (uint32_t)brow * 128;

    float acc[4][4][4];
#pragma unroll
    for (int mt = 0; mt < 4; mt++)
#pragma unroll
        for (int nt = 0; nt < 4; nt++)
#pragma unroll
            for (int c = 0; c < 4; c++) acc[mt][nt][c] = 0.0f;

    float rowsum = 0.0f;
    float4 ra[8], rb[4];
#pragma unroll
    for (int i = 0; i < 8; i++) ra[i] = *(const float4*)(Ap + i * 4);
#pragma unroll
    for (int i = 0; i < 4; i++) rb[i] = *(const float4*)(Bp + i * 4);

    for (int k0 = 0; k0 < SK; k0 += 32) {
#pragma unroll
        for (int i = 0; i < 8; i++) {
            rowsum += ra[i].x + ra[i].y + ra[i].z + ra[i].w;
            const int idx = tid * 32 + ((i ^ swzA) << 2);
            *(uint4*)&As[idx] = make_uint4(f2tf(ra[i].x), f2tf(ra[i].y),
                                           f2tf(ra[i].z), f2tf(ra[i].w));
        }
#pragma unroll
        for (int i = 0; i < 4; i++) {
            const int g = sgB0 + i;
            const int idx = srB * 32 + ((g ^ swzB) << 2);
            *(uint4*)&Bs[idx] = make_uint4(f2tf(rb[i].x), f2tf(rb[i].y),
                                           f2tf(rb[i].z), f2tf(rb[i].w));
        }
        __syncthreads();

        if (k0 + 32 < SK) {
            Ap += 32; Bp += 32;
#pragma unroll
            for (int i = 0; i < 8; i++) ra[i] = *(const float4*)(Ap + i * 4);
#pragma unroll
            for (int i = 0; i < 4; i++) rb[i] = *(const float4*)(Bp + i * 4);
        }

#pragma unroll
        for (int s = 0; s < 4; s++) {
            const uint32_t gA = (uint32_t)(((2 * s + agh) ^ lswz) << 4);
            const uint32_t gB = (uint32_t)(((2 * s + bgh) ^ lswz) << 4);
            uint32_t af[4][4], bf[4][2];
#pragma unroll
            for (int mt = 0; mt < 4; mt++)
                LDSM4(af[mt][0], af[mt][1], af[mt][2], af[mt][3],
                      aBase + (uint32_t)(mt * 2048) + gA);
            LDSM4(bf[0][0], bf[0][1], bf[1][0], bf[1][1], bBase + gB);
            LDSM4(bf[2][0], bf[2][1], bf[3][0], bf[3][1], bBase + 2048u + gB);
#pragma unroll
            for (int mt = 0; mt < 4; mt++)
#pragma unroll
                for (int nt = 0; nt < 4; nt++)
                    MMA8(acc[mt][nt], af[mt], bf[nt][0], bf[nt][1]);
        }
        __syncthreads();
    }

    // denominators: thread tid owns full attn row (l0 + tid)
    float* ds = (float*)As;
    ds[tid] = rowsum;
    __syncthreads();

#pragma unroll
    for (int mt = 0; mt < 4; mt++) {
        const int rl = wm0 + mt * 16 + (lane >> 2);
        const float inv0 = __fdividef(1.0f, ds[rl]     + 1e-4f);
        const float inv1 = __fdividef(1.0f, ds[rl + 8] + 1e-4f);
        const int l = l0 + rl;
#pragma unroll
        for (int nt = 0; nt < 4; nt++) {
            const int c = wn0 + nt * 8 + 2 * (lane & 3);
            *(float2*)&g_ctx[(size_t)(l * BATCH + b) * EMB + h * HD + c] =
                make_float2(acc[mt][nt][0] * inv0, acc[mt][nt][1] * inv0);
            *(float2*)&g_ctx[(size_t)((l + 8) * BATCH + b) * EMB + h * HD + c] =
                make_float2(acc[mt][nt][2] * inv1, acc[mt][nt][3] * inv1);
        }
    }
}

// =====================================================================
// out-projection (tf32): grid (8, 32), 256 thr
// =====================================================================
__global__ __launch_bounds__(256, 1) void k_outproj_t(
    const float* __restrict__ Wo, const float* __restrict__ bo,
    float* __restrict__ out)
{
    const int m0 = blockIdx.y * 128, n0 = blockIdx.x * 128;

    float acc[4][4][4];
    gemm_v1(g_ctx + (size_t)m0 * EMB, EMB, Wo + (size_t)n0 * EMB, EMB, EMB, acc);

    const int lane = threadIdx.x & 31, warp = threadIdx.x >> 5;
    const int wm0 = (warp >> 2) * 64, wn0 = (warp & 3) * 32;

#pragma unroll
    for (int nt = 0; nt < 4; nt++) {
        const int c = n0 + wn0 + nt * 8 + 2 * (lane & 3);
        const float b0 = bo[c], b1 = bo[c + 1];
#pragma unroll
        for (int mt = 0; mt < 4; mt++) {
            const int r = m0 + wm0 + mt * 16 + (lane >> 2);
            *(float2*)&out[(size_t)r * EMB + c] =
                make_float2(acc[mt][nt][0] + b0, acc[mt][nt][1] + b1);
            *(float2*)&out[(size_t)(r + 8) * EMB + c] =
                make_float2(acc[mt][nt][2] + b0, acc[mt][nt][3] + b1);
        }
    }
}

// =====================================================================
extern "C" void kernel_launch(void* const* d_in, const int* in_sizes, int n_in,
                              void* d_out, int out_size)
{
    (void)in_sizes; (void)n_in; (void)out_size;
    const float* q    = (const float*)d_in[0];
    const float* k    = (const float*)d_in[1];
    const float* v    = (const float*)d_in[2];
    const float* Wqkv = (const float*)d_in[3];
    const float* bqkv = (const float*)d_in[4];
    const float* Wo   = (const float*)d_in[5];
    const float* bo   = (const float*)d_in[6];
    float* out    = (float*)d_out;
    float* outAvg = out + (size_t)LQ * BATCH * EMB;

    k_inproj_t<<<dim3(EMB / 128, MR / 128, 3), 256>>>(q, k, v, Wqkv, bqkv);
    k_scores_t<<<dim3(SK / 128, LQ / 128, BHn), 256>>>();
    k_avg<<<(int)(((size_t)BATCH * LQ * SK / 4) / 256), 256>>>(outAvg);
    k_pv_t<<<dim3(LQ / 128, BHn), 128>>>();
    k_outproj_t<<<dim3(EMB / 128, MR / 128), 256>>>(Wo, bo, out);
}

// round 3
// speedup vs baseline: 2.4538x; 1.1425x over previous
#include <cuda_runtime.h>
#include <cuda_fp16.h>
#include <math.h>
#include <stdint.h>

// Problem constants
#define LQ    2048
#define BATCH 2
#define EMB   1024
#define NH    16
#define HD    64
#define SK    2048
#define BHn   32
#define MR    4096

// ---------------- scratch (device globals) ----------------
__device__ float g_q[BHn * LQ * HD];               // [bh][l][d], pre-scaled by 1/8
__device__ float g_k[BHn * SK * HD];               // [bh][s][d]
__device__ float g_vt[BHn * HD * SK];              // [bh][d][s]  (V transposed)
__device__ __half g_attnh[(size_t)BHn * LQ * SK];  // 256 MB fp16 sigmoid scores (avg only)
__device__ float g_ctx[MR * EMB];                  // attention out, (L,B,E) rows

// ---------------- tf32 MMA helpers ----------------
__device__ __forceinline__ uint32_t f2tf(float f) {
    uint32_t u;
    asm("cvt.rna.tf32.f32 %0, %1;" : "=r"(u) : "f"(f));
    return u;
}

#define LDSM4(R0,R1,R2,R3,ADDR) \
    asm volatile("ldmatrix.sync.aligned.m8n8.x4.shared.b16 {%0,%1,%2,%3}, [%4];" \
        : "=r"(R0), "=r"(R1), "=r"(R2), "=r"(R3) : "r"(ADDR))

#define MMA8(C,A,B0,B1) \
    asm volatile("mma.sync.aligned.m16n8k8.row.col.f32.tf32.tf32.f32 " \
        "{%0,%1,%2,%3},{%4,%5,%6,%7},{%8,%9},{%0,%1,%2,%3};" \
        : "+f"((C)[0]), "+f"((C)[1]), "+f"((C)[2]), "+f"((C)[3]) \
        : "r"((A)[0]), "r"((A)[1]), "r"((A)[2]), "r"((A)[3]), "r"(B0), "r"(B1))

__device__ __forceinline__ float fsigmoid(float x) {
    return __fdividef(1.0f, 1.0f + __expf(-x));
}

// =====================================================================
// V1 core: CTA tile 128x128, BK=32, 256 threads (8 warps 2x4, warp 64x32)
// =====================================================================
__device__ __forceinline__ void gemm_v1(
    const float* __restrict__ Ag, int lda,
    const float* __restrict__ Bg, int ldb,
    int K, float (&acc)[4][4][4])
{
    __shared__ uint32_t As[128 * 32];
    __shared__ uint32_t Bs[128 * 32];

    const int tid  = threadIdx.x;
    const int lane = tid & 31, warp = tid >> 5;
    const int wm0 = (warp >> 2) * 64;
    const int wn0 = (warp & 3) * 32;

    const int srow = tid >> 1;
    const int sg0  = (tid & 1) * 4;
    const int swz  = srow & 7;
    const float* Ap = Ag + (size_t)srow * lda + sg0 * 4;
    const float* Bp = Bg + (size_t)srow * ldb + sg0 * 4;

    const int arow = wm0 + (lane & 15);
    const int agh  = lane >> 4;
    const int brow = wn0 + (lane & 7) + ((lane >> 4) << 3);
    const int bgh  = (lane >> 3) & 1;
    const int lswz = lane & 7;
    const uint32_t as_b = (uint32_t)__cvta_generic_to_shared(As);
    const uint32_t bs_b = (uint32_t)__cvta_generic_to_shared(Bs);
    const uint32_t aBase = as_b + (uint32_t)arow * 128;
    const uint32_t bBase = bs_b + (uint32_t)brow * 128;

#pragma unroll
    for (int mt = 0; mt < 4; mt++)
#pragma unroll
        for (int nt = 0; nt < 4; nt++)
#pragma unroll
            for (int c = 0; c < 4; c++) acc[mt][nt][c] = 0.0f;

    float4 ra[4], rb[4];
#pragma unroll
    for (int i = 0; i < 4; i++) {
        ra[i] = *(const float4*)(Ap + i * 4);
        rb[i] = *(const float4*)(Bp + i * 4);
    }

    for (int k0 = 0; k0 < K; k0 += 32) {
#pragma unroll
        for (int i = 0; i < 4; i++) {
            const int g = sg0 + i;
            const int idx = srow * 32 + ((g ^ swz) << 2);
            *(uint4*)&As[idx] = make_uint4(f2tf(ra[i].x), f2tf(ra[i].y), f2tf(ra[i].z), f2tf(ra[i].w));
            *(uint4*)&Bs[idx] = make_uint4(f2tf(rb[i].x), f2tf(rb[i].y), f2tf(rb[i].z), f2tf(rb[i].w));
        }
        __syncthreads();

        if (k0 + 32 < K) {
            Ap += 32; Bp += 32;
#pragma unroll
            for (int i = 0; i < 4; i++) {
                ra[i] = *(const float4*)(Ap + i * 4);
                rb[i] = *(const float4*)(Bp + i * 4);
            }
        }

#pragma unroll
        for (int s = 0; s < 4; s++) {
            const uint32_t gA = (uint32_t)(((2 * s + agh) ^ lswz) << 4);
            const uint32_t gB = (uint32_t)(((2 * s + bgh) ^ lswz) << 4);
            uint32_t af[4][4], bf[4][2];
#pragma unroll
            for (int mt = 0; mt < 4; mt++)
                LDSM4(af[mt][0], af[mt][1], af[mt][2], af[mt][3],
                      aBase + (uint32_t)(mt * 2048) + gA);
            LDSM4(bf[0][0], bf[0][1], bf[1][0], bf[1][1], bBase + gB);
            LDSM4(bf[2][0], bf[2][1], bf[3][0], bf[3][1], bBase + 2048u + gB);
#pragma unroll
            for (int mt = 0; mt < 4; mt++)
#pragma unroll
                for (int nt = 0; nt < 4; nt++)
                    MMA8(acc[mt][nt], af[mt], bf[nt][0], bf[nt][1]);
        }
        __syncthreads();
    }
}

// =====================================================================
// in-projection (tf32): grid (8, 32, 3), 256 thr
// =====================================================================
__global__ __launch_bounds__(256, 1) void k_inproj_t(
    const float* __restrict__ qin, const float* __restrict__ kin,
    const float* __restrict__ vin, const float* __restrict__ W,
    const float* __restrict__ bias)
{
    const int p = blockIdx.z;
    const float* X  = (p == 0) ? qin : (p == 1) ? kin : vin;
    const float* Wp = W + (size_t)p * EMB * EMB;
    const float* bp = bias + p * EMB;
    const float scale = (p == 0) ? 0.125f : 1.0f;
    const int m0 = blockIdx.y * 128, n0 = blockIdx.x * 128;

    float acc[4][4][4];
    gemm_v1(X + (size_t)m0 * EMB, EMB, Wp + (size_t)n0 * EMB, EMB, EMB, acc);

    const int lane = threadIdx.x & 31, warp = threadIdx.x >> 5;
    const int wm0 = (warp >> 2) * 64, wn0 = (warp & 3) * 32;

#pragma unroll
    for (int nt = 0; nt < 4; nt++) {
        const int c = n0 + wn0 + nt * 8 + 2 * (lane & 3);
        const float b0 = bp[c], b1 = bp[c + 1];
        const int h = c >> 6, d = c & 63;
#pragma unroll
        for (int mt = 0; mt < 4; mt++) {
            const int r = m0 + wm0 + mt * 16 + (lane >> 2);
#pragma unroll
            for (int half = 0; half < 2; half++) {
                const int rr = r + half * 8;
                const float v0 = (acc[mt][nt][half * 2 + 0] + b0) * scale;
                const float v1 = (acc[mt][nt][half * 2 + 1] + b1) * scale;
                const int l = rr >> 1, bb = rr & 1;
                const int bh = bb * NH + h;
                if (p == 0)
                    *(float2*)&g_q[((size_t)bh * LQ + l) * HD + d] = make_float2(v0, v1);
                else if (p == 1)
                    *(float2*)&g_k[((size_t)bh * SK + l) * HD + d] = make_float2(v0, v1);
                else {
                    g_vt[((size_t)bh * HD + d)     * SK + l] = v0;
                    g_vt[((size_t)bh * HD + d + 1) * SK + l] = v1;
                }
            }
        }
    }
}

// =====================================================================
// FUSED attention: per CTA (l-tile 128, bh). Loop s-tiles of 64:
//   QK^T tf32 MMA -> sigmoid -> {fp16 attn store, tf32 P smem, rowsum}
//   -> P@V^T tf32 MMA accumulate. Epilogue: ctx = acc / (rowsum+1e-4).
// 256 thr, 8 warps (2 m x 4 n), warp tile 64x16 on both GEMMs.
// Dynamic smem: Qs 32K | Ks 16K | Vs 16K | Ps 32K | ds 512B
// =====================================================================
__global__ __launch_bounds__(256, 1) void k_attn_fused()
{
    extern __shared__ uint32_t sm[];
    uint32_t* Qs = sm;                   // 128x64
    uint32_t* Ks = sm + 8192;            // 64x64
    uint32_t* Vs = sm + 12288;           // 64x64
    uint32_t* Ps = sm + 16384;           // 128x64
    float*    ds = (float*)(sm + 24576); // 128

    const int bh = blockIdx.y;
    const int l0 = blockIdx.x * 128;
    const int b = bh >> 4, h = bh & 15;
    const int tid = threadIdx.x, lane = tid & 31, warp = tid >> 5;
    const int wm = (warp >> 2) * 64;     // m (l) offset
    const int wq = (warp & 3) * 16;      // n offset (s for QK, d for PV)

    // ---- load Q tile (128x64) into swizzled smem, cvt tf32 ----
    {
        const int row = tid >> 1, gb = (tid & 1) * 8, sw = row & 7;
        const float* qp = g_q + ((size_t)bh * LQ + l0 + row) * HD + gb * 4;
#pragma unroll
        for (int i = 0; i < 8; i++) {
            float4 v = *(const float4*)(qp + i * 4);
            *(uint4*)&Qs[row * 64 + (((gb + i) ^ sw) << 2)] =
                make_uint4(f2tf(v.x), f2tf(v.y), f2tf(v.z), f2tf(v.w));
        }
    }

    // staging for K/V tiles (64 rows x 64 cols)
    const int krow = tid >> 2, kg0 = (tid & 3) * 4, ksw = krow & 7;
    const float* kp = g_k  + ((size_t)bh * SK + krow) * HD + kg0 * 4;
    const float* vp = g_vt + ((size_t)bh * HD + krow) * SK + kg0 * 4;

    // ldmatrix addressing (row width 256B = 16 granules)
    const int aRow = wm + (lane & 15);
    const int agh  = lane >> 4;
    const int lsw  = lane & 7;
    const int bRow = wq + (lane & 7) + ((lane >> 4) << 3);
    const int bgh  = (lane >> 3) & 1;
    const uint32_t aQ = (uint32_t)__cvta_generic_to_shared(Qs) + (uint32_t)aRow * 256;
    const uint32_t aP = (uint32_t)__cvta_generic_to_shared(Ps) + (uint32_t)aRow * 256;
    const uint32_t bK = (uint32_t)__cvta_generic_to_shared(Ks) + (uint32_t)bRow * 256;
    const uint32_t bV = (uint32_t)__cvta_generic_to_shared(Vs) + (uint32_t)bRow * 256;

    float acc_qk[4][2][4], acc_pv[4][2][4], rsum[4][2];
#pragma unroll
    for (int mt = 0; mt < 4; mt++) {
        rsum[mt][0] = rsum[mt][1] = 0.0f;
#pragma unroll
        for (int nt = 0; nt < 2; nt++)
#pragma unroll
            for (int c = 0; c < 4; c++) {
                acc_qk[mt][nt][c] = 0.0f;
                acc_pv[mt][nt][c] = 0.0f;
            }
    }

    float4 rk[4], rv[4];
#pragma unroll
    for (int i = 0; i < 4; i++) {
        rk[i] = *(const float4*)(kp + i * 4);
        rv[i] = *(const float4*)(vp + i * 4);
    }

    const int r0b = wm + (lane >> 2);
    const int c0b = wq + 2 * (lane & 3);

    for (int it = 0; it < 32; it++) {
        const int s0 = it * 64;
        __syncthreads();   // previous PV done reading Ks/Vs
#pragma unroll
        for (int i = 0; i < 4; i++) {
            const int idx = krow * 64 + (((kg0 + i) ^ ksw) << 2);
            *(uint4*)&Ks[idx] = make_uint4(f2tf(rk[i].x), f2tf(rk[i].y), f2tf(rk[i].z), f2tf(rk[i].w));
            *(uint4*)&Vs[idx] = make_uint4(f2tf(rv[i].x), f2tf(rv[i].y), f2tf(rv[i].z), f2tf(rv[i].w));
        }
        __syncthreads();

        if (it < 31) {
            kp += 64 * HD; vp += 64;
#pragma unroll
            for (int i = 0; i < 4; i++) {
                rk[i] = *(const float4*)(kp + i * 4);
                rv[i] = *(const float4*)(vp + i * 4);
            }
        }

        // ---- QK^T MMA (K-dim 64, 8 k8 substeps) ----
#pragma unroll
        for (int ss = 0; ss < 8; ss++) {
            const uint32_t offA = (uint32_t)(((2 * ss + agh) ^ lsw) << 4);
            const uint32_t offB = (uint32_t)(((2 * ss + bgh) ^ lsw) << 4);
            uint32_t af[4][4], bf[4];
#pragma unroll
            for (int mt = 0; mt < 4; mt++)
                LDSM4(af[mt][0], af[mt][1], af[mt][2], af[mt][3],
                      aQ + (uint32_t)(mt * 4096) + offA);
            LDSM4(bf[0], bf[1], bf[2], bf[3], bK + offB);
#pragma unroll
            for (int mt = 0; mt < 4; mt++) {
                MMA8(acc_qk[mt][0], af[mt], bf[0], bf[1]);
                MMA8(acc_qk[mt][1], af[mt], bf[2], bf[3]);
            }
        }

        // ---- sigmoid epilogue: fp16 attn, tf32 P, rowsums ----
#pragma unroll
        for (int mt = 0; mt < 4; mt++) {
            const int r0 = r0b + mt * 16;
            float rs0 = 0.0f, rs1 = 0.0f;
#pragma unroll
            for (int nt = 0; nt < 2; nt++) {
                const int c0 = c0b + nt * 8;
                const float v0 = fsigmoid(acc_qk[mt][nt][0]);
                const float v1 = fsigmoid(acc_qk[mt][nt][1]);
                const float v2 = fsigmoid(acc_qk[mt][nt][2]);
                const float v3 = fsigmoid(acc_qk[mt][nt][3]);
                acc_qk[mt][nt][0] = 0.0f; acc_qk[mt][nt][1] = 0.0f;
                acc_qk[mt][nt][2] = 0.0f; acc_qk[mt][nt][3] = 0.0f;
                rs0 += v0 + v1; rs1 += v2 + v3;
                *(half2*)&g_attnh[((size_t)bh * LQ + l0 + r0) * SK + s0 + c0] =
                    __floats2half2_rn(v0, v1);
                *(half2*)&g_attnh[((size_t)bh * LQ + l0 + r0 + 8) * SK + s0 + c0] =
                    __floats2half2_rn(v2, v3);
                const int g = c0 >> 2;
                const int idx = r0 * 64 + ((g ^ (r0 & 7)) << 2) + (c0 & 3);
                *(uint2*)&Ps[idx]       = make_uint2(f2tf(v0), f2tf(v1));
                *(uint2*)&Ps[idx + 512] = make_uint2(f2tf(v2), f2tf(v3));
            }
            rsum[mt][0] += rs0; rsum[mt][1] += rs1;
        }
        __syncthreads();   // Ps ready

        // ---- P @ V^T MMA ----
#pragma unroll
        for (int ss = 0; ss < 8; ss++) {
            const uint32_t offA = (uint32_t)(((2 * ss + agh) ^ lsw) << 4);
            const uint32_t offB = (uint32_t)(((2 * ss + bgh) ^ lsw) << 4);
            uint32_t af[4][4], bf[4];
#pragma unroll
            for (int mt = 0; mt < 4; mt++)
                LDSM4(af[mt][0], af[mt][1], af[mt][2], af[mt][3],
                      aP + (uint32_t)(mt * 4096) + offA);
            LDSM4(bf[0], bf[1], bf[2], bf[3], bV + offB);
#pragma unroll
            for (int mt = 0; mt < 4; mt++) {
                MMA8(acc_pv[mt][0], af[mt], bf[0], bf[1]);
                MMA8(acc_pv[mt][1], af[mt], bf[2], bf[3]);
            }
        }
    }

    // ---- denominators: reduce rsum across quads + 4 n-warps ----
    __syncthreads();
    if (tid < 128) ds[tid] = 0.0f;
    __syncthreads();
#pragma unroll
    for (int mt = 0; mt < 4; mt++)
#pragma unroll
        for (int hh = 0; hh < 2; hh++) {
            float v = rsum[mt][hh];
            v += __shfl_xor_sync(0xffffffffu, v, 1);
            v += __shfl_xor_sync(0xffffffffu, v, 2);
            if ((lane & 3) == 0)
                atomicAdd(&ds[wm + mt * 16 + (lane >> 2) + hh * 8], v);
        }
    __syncthreads();

    // ---- output: ctx = acc_pv / (den + 1e-4) ----
#pragma unroll
    for (int mt = 0; mt < 4; mt++) {
        const int rl = wm + mt * 16 + (lane >> 2);
        const float inv0 = __fdividef(1.0f, ds[rl]     + 1e-4f);
        const float inv1 = __fdividef(1.0f, ds[rl + 8] + 1e-4f);
        const int l = l0 + rl;
#pragma unroll
        for (int nt = 0; nt < 2; nt++) {
            const int c = wq + nt * 8 + 2 * (lane & 3);
            *(float2*)&g_ctx[(size_t)(l * BATCH + b) * EMB + h * HD + c] =
                make_float2(acc_pv[mt][nt][0] * inv0, acc_pv[mt][nt][1] * inv0);
            *(float2*)&g_ctx[(size_t)((l + 8) * BATCH + b) * EMB + h * HD + c] =
                make_float2(acc_pv[mt][nt][2] * inv1, acc_pv[mt][nt][3] * inv1);
        }
    }
}

// =====================================================================
// avg_weights from fp16 attn: thread handles 8 s-elems. grid 4096, 256 thr
// =====================================================================
__global__ __launch_bounds__(256) void k_avg_h(float* __restrict__ outAvg)
{
    const size_t t = (size_t)blockIdx.x * 256 + threadIdx.x;  // 8-elem group
    const int s8 = (int)(t & (SK / 8 - 1));
    const int l  = (int)((t >> 8) & (LQ - 1));
    const int b  = (int)(t >> 19);
    float acc[8] = {0, 0, 0, 0, 0, 0, 0, 0};
#pragma unroll
    for (int h = 0; h < NH; h++) {
        const uint4 u = *(const uint4*)&g_attnh[((size_t)(b * NH + h) * LQ + l) * SK + s8 * 8];
        const half2* p = (const half2*)&u;
#pragma unroll
        for (int j = 0; j < 4; j++) {
            const float2 f = __half22float2(p[j]);
            acc[2 * j]     += f.x;
            acc[2 * j + 1] += f.y;
        }
    }
    float* o = outAvg + t * 8;
    const float inv = 1.0f / NH;
    *(float4*)o       = make_float4(acc[0] * inv, acc[1] * inv, acc[2] * inv, acc[3] * inv);
    *(float4*)(o + 4) = make_float4(acc[4] * inv, acc[5] * inv, acc[6] * inv, acc[7] * inv);
}

// =====================================================================
// out-projection (tf32): grid (8, 32), 256 thr
// =====================================================================
__global__ __launch_bounds__(256, 1) void k_outproj_t(
    const float* __restrict__ Wo, const float* __restrict__ bo,
    float* __restrict__ out)
{
    const int m0 = blockIdx.y * 128, n0 = blockIdx.x * 128;

    float acc[4][4][4];
    gemm_v1(g_ctx + (size_t)m0 * EMB, EMB, Wo + (size_t)n0 * EMB, EMB, EMB, acc);

    const int lane = threadIdx.x & 31, warp = threadIdx.x >> 5;
    const int wm0 = (warp >> 2) * 64, wn0 = (warp & 3) * 32;

#pragma unroll
    for (int nt = 0; nt < 4; nt++) {
        const int c = n0 + wn0 + nt * 8 + 2 * (lane & 3);
        const float b0 = bo[c], b1 = bo[c + 1];
#pragma unroll
        for (int mt = 0; mt < 4; mt++) {
            const int r = m0 + wm0 + mt * 16 + (lane >> 2);
            *(float2*)&out[(size_t)r * EMB + c] =
                make_float2(acc[mt][nt][0] + b0, acc[mt][nt][1] + b1);
            *(float2*)&out[(size_t)(r + 8) * EMB + c] =
                make_float2(acc[mt][nt][2] + b0, acc[mt][nt][3] + b1);
        }
    }
}

// =====================================================================
#define FUSED_SMEM (24576 * 4 + 512)   // 98816 bytes

extern "C" void kernel_launch(void* const* d_in, const int* in_sizes, int n_in,
                              void* d_out, int out_size)
{
    (void)in_sizes; (void)n_in; (void)out_size;
    const float* q    = (const float*)d_in[0];
    const float* k    = (const float*)d_in[1];
    const float* v    = (const float*)d_in[2];
    const float* Wqkv = (const float*)d_in[3];
    const float* bqkv = (const float*)d_in[4];
    const float* Wo   = (const float*)d_in[5];
    const float* bo   = (const float*)d_in[6];
    float* out    = (float*)d_out;
    float* outAvg = out + (size_t)LQ * BATCH * EMB;

    cudaFuncSetAttribute(k_attn_fused,
                         cudaFuncAttributeMaxDynamicSharedMemorySize, FUSED_SMEM);

    k_inproj_t<<<dim3(EMB / 128, MR / 128, 3), 256>>>(q, k, v, Wqkv, bqkv);
    k_attn_fused<<<dim3(LQ / 128, BHn), 256, FUSED_SMEM>>>();
    k_avg_h<<<4096, 256>>>(outAvg);
    k_outproj_t<<<dim3(EMB / 128, MR / 128), 256>>>(Wo, bo, out);
}

// round 4
// speedup vs baseline: 3.0585x; 1.2464x over previous
#include <cuda_runtime.h>
#include <cuda_fp16.h>
#include <math.h>
#include <stdint.h>

// Problem constants
#define LQ    2048
#define BATCH 2
#define EMB   1024
#define NH    16
#define HD    64
#define SK    2048
#define BHn   32
#define MR    4096

// ---------------- scratch (device globals) ----------------
__device__ __half g_qh[BHn * LQ * HD];              // [bh][l][d], pre-scaled 1/8
__device__ __half g_kh[BHn * SK * HD];              // [bh][s][d]
__device__ __half g_vth[BHn * HD * SK];             // [bh][d][s]
__device__ __half g_attnh[(size_t)BHn * LQ * SK];   // 256 MB sigmoid scores (avg only)
__device__ __half g_ctxh[MR * EMB];                 // attention out, (L,B,E) rows

// ---------------- helpers ----------------
__device__ __forceinline__ uint32_t f2h2(float a, float b) {
    half2 h = __floats2half2_rn(a, b);
    return *reinterpret_cast<uint32_t*>(&h);
}

#define LDSM4(R0,R1,R2,R3,ADDR) \
    asm volatile("ldmatrix.sync.aligned.m8n8.x4.shared.b16 {%0,%1,%2,%3}, [%4];" \
        : "=r"(R0), "=r"(R1), "=r"(R2), "=r"(R3) : "r"(ADDR))

#define MMAH(C,A,B0,B1) \
    asm volatile("mma.sync.aligned.m16n8k16.row.col.f32.f16.f16.f32 " \
        "{%0,%1,%2,%3},{%4,%5,%6,%7},{%8,%9},{%0,%1,%2,%3};" \
        : "+f"((C)[0]), "+f"((C)[1]), "+f"((C)[2]), "+f"((C)[3]) \
        : "r"((A)[0]), "r"((A)[1]), "r"((A)[2]), "r"((A)[3]), "r"(B0), "r"(B1))

__device__ __forceinline__ float fsigmoid(float x) {
    return __fdividef(1.0f, 1.0f + __expf(-x));
}

// =====================================================================
// fp16 GEMM core: CTA 128x128, BK=64 halves, 256 thr, 8 warps (2x4),
// warp tile 64x32 (4 mt x 4 nt of m16n8k16). A row-major MxK, B row-major
// NxK (col-major op). Smem rows 128B, 8x16B granules, XOR swizzle.
// AH: A source is fp16 (direct copy) else fp32 (convert on store).
// =====================================================================
template<bool AH>
__device__ __forceinline__ void gemm_h(
    const void* __restrict__ Agv, int lda,
    const float* __restrict__ Bg, int ldb,
    int K, float (&acc)[4][4][4])
{
    __shared__ uint4 As16[1024];   // 128 rows x 8 granules
    __shared__ uint4 Bs16[1024];

    const int tid = threadIdx.x;
    const int lane = tid & 31, warp = tid >> 5;
    const int wm0 = (warp >> 2) * 64, wn0 = (warp & 3) * 32;

    const int srow = tid >> 1, sg0 = (tid & 1) * 4, swz = srow & 7;
    const __half* Ah = (const __half*)Agv + (size_t)srow * lda + sg0 * 8;
    const float*  Af = (const float*)Agv + (size_t)srow * lda + sg0 * 8;
    const float*  Bp = Bg + (size_t)srow * ldb + sg0 * 8;

    const int arow = wm0 + (lane & 15), agh = lane >> 4, lsw = lane & 7;
    const int brow = wn0 + (lane & 7) + ((lane >> 4) << 3), bgh = (lane >> 3) & 1;
    const uint32_t aBase = (uint32_t)__cvta_generic_to_shared(As16) + (uint32_t)arow * 128;
    const uint32_t bBase = (uint32_t)__cvta_generic_to_shared(Bs16) + (uint32_t)brow * 128;

#pragma unroll
    for (int mt = 0; mt < 4; mt++)
#pragma unroll
        for (int nt = 0; nt < 4; nt++)
#pragma unroll
            for (int c = 0; c < 4; c++) acc[mt][nt][c] = 0.0f;

    uint4 ua[4]; float4 raf[8], rbf[8];
#pragma unroll
    for (int i = 0; i < 4; i++) {
        if (AH) ua[i] = *(const uint4*)(Ah + i * 8);
        else {
            raf[2 * i]     = *(const float4*)(Af + i * 8);
            raf[2 * i + 1] = *(const float4*)(Af + i * 8 + 4);
        }
        rbf[2 * i]     = *(const float4*)(Bp + i * 8);
        rbf[2 * i + 1] = *(const float4*)(Bp + i * 8 + 4);
    }

    for (int k0 = 0; k0 < K; k0 += 64) {
#pragma unroll
        for (int i = 0; i < 4; i++) {
            const int idx = srow * 8 + ((sg0 + i) ^ swz);
            if (AH) As16[idx] = ua[i];
            else As16[idx] = make_uint4(
                f2h2(raf[2*i].x, raf[2*i].y), f2h2(raf[2*i].z, raf[2*i].w),
                f2h2(raf[2*i+1].x, raf[2*i+1].y), f2h2(raf[2*i+1].z, raf[2*i+1].w));
            Bs16[idx] = make_uint4(
                f2h2(rbf[2*i].x, rbf[2*i].y), f2h2(rbf[2*i].z, rbf[2*i].w),
                f2h2(rbf[2*i+1].x, rbf[2*i+1].y), f2h2(rbf[2*i+1].z, rbf[2*i+1].w));
        }
        __syncthreads();

        if (k0 + 64 < K) {
            Ah += 64; Af += 64; Bp += 64;
#pragma unroll
            for (int i = 0; i < 4; i++) {
                if (AH) ua[i] = *(const uint4*)(Ah + i * 8);
                else {
                    raf[2 * i]     = *(const float4*)(Af + i * 8);
                    raf[2 * i + 1] = *(const float4*)(Af + i * 8 + 4);
                }
                rbf[2 * i]     = *(const float4*)(Bp + i * 8);
                rbf[2 * i + 1] = *(const float4*)(Bp + i * 8 + 4);
            }
        }

#pragma unroll
        for (int ss = 0; ss < 4; ss++) {
            const uint32_t offA = (uint32_t)(((2 * ss + agh) ^ lsw) << 4);
            const uint32_t offB = (uint32_t)(((2 * ss + bgh) ^ lsw) << 4);
            uint32_t af[4][4], bf0[4], bf1[4];
#pragma unroll
            for (int mt = 0; mt < 4; mt++)
                LDSM4(af[mt][0], af[mt][1], af[mt][2], af[mt][3],
                      aBase + (uint32_t)(mt * 2048) + offA);
            LDSM4(bf0[0], bf0[1], bf0[2], bf0[3], bBase + offB);
            LDSM4(bf1[0], bf1[1], bf1[2], bf1[3], bBase + 2048u + offB);
#pragma unroll
            for (int mt = 0; mt < 4; mt++) {
                MMAH(acc[mt][0], af[mt], bf0[0], bf0[1]);
                MMAH(acc[mt][1], af[mt], bf0[2], bf0[3]);
                MMAH(acc[mt][2], af[mt], bf1[0], bf1[1]);
                MMAH(acc[mt][3], af[mt], bf1[2], bf1[3]);
            }
        }
        __syncthreads();
    }
}

// =====================================================================
// in-projection (fp16 MMA): grid (8, 32, 3), 256 thr -> fp16 q/k/vt
// =====================================================================
__global__ __launch_bounds__(256, 1) void k_inproj_h(
    const float* __restrict__ qin, const float* __restrict__ kin,
    const float* __restrict__ vin, const float* __restrict__ W,
    const float* __restrict__ bias)
{
    const int p = blockIdx.z;
    const float* X  = (p == 0) ? qin : (p == 1) ? kin : vin;
    const float* Wp = W + (size_t)p * EMB * EMB;
    const float* bp = bias + p * EMB;
    const float scale = (p == 0) ? 0.125f : 1.0f;
    const int m0 = blockIdx.y * 128, n0 = blockIdx.x * 128;

    float acc[4][4][4];
    gemm_h<false>(X + (size_t)m0 * EMB, EMB, Wp + (size_t)n0 * EMB, EMB, EMB, acc);

    const int lane = threadIdx.x & 31, warp = threadIdx.x >> 5;
    const int wm0 = (warp >> 2) * 64, wn0 = (warp & 3) * 32;

#pragma unroll
    for (int nt = 0; nt < 4; nt++) {
        const int c = n0 + wn0 + nt * 8 + 2 * (lane & 3);
        const float b0 = bp[c], b1 = bp[c + 1];
        const int h = c >> 6, d = c & 63;
#pragma unroll
        for (int mt = 0; mt < 4; mt++) {
            const int r = m0 + wm0 + mt * 16 + (lane >> 2);
#pragma unroll
            for (int half_ = 0; half_ < 2; half_++) {
                const int rr = r + half_ * 8;
                const float v0 = (acc[mt][nt][half_ * 2 + 0] + b0) * scale;
                const float v1 = (acc[mt][nt][half_ * 2 + 1] + b1) * scale;
                const int l = rr >> 1, bb = rr & 1;
                const int bh = bb * NH + h;
                if (p == 0)
                    *(half2*)&g_qh[((size_t)bh * LQ + l) * HD + d] = __floats2half2_rn(v0, v1);
                else if (p == 1)
                    *(half2*)&g_kh[((size_t)bh * SK + l) * HD + d] = __floats2half2_rn(v0, v1);
                else {
                    g_vth[((size_t)bh * HD + d)     * SK + l] = __float2half(v0);
                    g_vth[((size_t)bh * HD + d + 1) * SK + l] = __float2half(v1);
                }
            }
        }
    }
}

// =====================================================================
// FUSED attention (fp16): per CTA (l-tile 128, bh). 32 s-tiles of 64:
// QK^T MMA -> sigmoid -> {fp16 attn store, P smem, rowsum} -> P@V^T MMA.
// 256 thr, 8 warps (2m x 4n), warp 64x16 both GEMMs.
// =====================================================================
__global__ __launch_bounds__(256, 1) void k_attn_fused_h()
{
    extern __shared__ uint4 smv[];
    uint4* Qs = smv;                 // 128x8 granules, 16KB
    uint4* Ks = smv + 1024;          // 64x8, 8KB
    uint4* Vs = smv + 1536;          // 64x8, 8KB
    uint4* Ps = smv + 2048;          // 128x8, 16KB
    float* ds = (float*)(smv + 3072);

    const int bh = blockIdx.y;
    const int l0 = blockIdx.x * 128;
    const int b = bh >> 4, h = bh & 15;
    const int tid = threadIdx.x, lane = tid & 31, warp = tid >> 5;
    const int wm = (warp >> 2) * 64;
    const int wq = (warp & 3) * 16;

    // ---- Q tile load: 128 rows x 8 granules (direct fp16 copy) ----
    {
        const int row = tid >> 1, sw = row & 7;
        const __half* qp = g_qh + ((size_t)bh * LQ + l0 + row) * HD;
#pragma unroll
        for (int i = 0; i < 4; i++) {
            const int g = (tid & 1) * 4 + i;
            Qs[row * 8 + (g ^ sw)] = *(const uint4*)(qp + g * 8);
        }
    }

    // K/V staging: 64 rows x 8 granules, 2 granules/thread
    const int krow = tid >> 2, ksw = krow & 7;
    const int kg0 = (tid & 3) * 2;
    const __half* kp = g_kh  + ((size_t)bh * SK + krow) * HD + kg0 * 8;
    const __half* vp = g_vth + ((size_t)bh * HD + krow) * SK + kg0 * 8;

    const int aRow = wm + (lane & 15), agh = lane >> 4, lsw = lane & 7;
    const int bRow = wq + (lane & 7) + ((lane >> 4) << 3), bgh = (lane >> 3) & 1;
    const uint32_t aQ = (uint32_t)__cvta_generic_to_shared(Qs) + (uint32_t)aRow * 128;
    const uint32_t aP = (uint32_t)__cvta_generic_to_shared(Ps) + (uint32_t)aRow * 128;
    const uint32_t bK = (uint32_t)__cvta_generic_to_shared(Ks) + (uint32_t)bRow * 128;
    const uint32_t bV = (uint32_t)__cvta_generic_to_shared(Vs) + (uint32_t)bRow * 128;
    uint32_t* Ps32 = (uint32_t*)Ps;

    float acc_qk[4][2][4], acc_pv[4][2][4], rsum[4][2];
#pragma unroll
    for (int mt = 0; mt < 4; mt++) {
        rsum[mt][0] = rsum[mt][1] = 0.0f;
#pragma unroll
        for (int nt = 0; nt < 2; nt++)
#pragma unroll
            for (int c = 0; c < 4; c++) {
                acc_qk[mt][nt][c] = 0.0f;
                acc_pv[mt][nt][c] = 0.0f;
            }
    }

    uint4 rk[2], rv[2];
#pragma unroll
    for (int i = 0; i < 2; i++) {
        rk[i] = *(const uint4*)(kp + i * 8);
        rv[i] = *(const uint4*)(vp + i * 8);
    }

    const int r0b = wm + (lane >> 2);
    const int c0b = wq + 2 * (lane & 3);

    for (int it = 0; it < 32; it++) {
        const int s0 = it * 64;
        __syncthreads();   // prev PV done with Ks/Vs/Ps
#pragma unroll
        for (int i = 0; i < 2; i++) {
            const int g = kg0 + i;
            Ks[krow * 8 + (g ^ ksw)] = rk[i];
            Vs[krow * 8 + (g ^ ksw)] = rv[i];
        }
        __syncthreads();

        if (it < 31) {
            kp += 64 * HD; vp += 64;
#pragma unroll
            for (int i = 0; i < 2; i++) {
                rk[i] = *(const uint4*)(kp + i * 8);
                rv[i] = *(const uint4*)(vp + i * 8);
            }
        }

        // ---- QK^T MMA (K=64 -> 4 k16 substeps) ----
#pragma unroll
        for (int ss = 0; ss < 4; ss++) {
            const uint32_t offA = (uint32_t)(((2 * ss + agh) ^ lsw) << 4);
            const uint32_t offB = (uint32_t)(((2 * ss + bgh) ^ lsw) << 4);
            uint32_t af[4][4], bf[4];
#pragma unroll
            for (int mt = 0; mt < 4; mt++)
                LDSM4(af[mt][0], af[mt][1], af[mt][2], af[mt][3],
                      aQ + (uint32_t)(mt * 2048) + offA);
            LDSM4(bf[0], bf[1], bf[2], bf[3], bK + offB);
#pragma unroll
            for (int mt = 0; mt < 4; mt++) {
                MMAH(acc_qk[mt][0], af[mt], bf[0], bf[1]);
                MMAH(acc_qk[mt][1], af[mt], bf[2], bf[3]);
            }
        }

        // ---- sigmoid epilogue ----
#pragma unroll
        for (int mt = 0; mt < 4; mt++) {
            const int r0 = r0b + mt * 16;
#pragma unroll
            for (int nt = 0; nt < 2; nt++) {
                const int c0 = c0b + nt * 8;
                const float v0 = fsigmoid(acc_qk[mt][nt][0]);
                const float v1 = fsigmoid(acc_qk[mt][nt][1]);
                const float v2 = fsigmoid(acc_qk[mt][nt][2]);
                const float v3 = fsigmoid(acc_qk[mt][nt][3]);
                acc_qk[mt][nt][0] = 0.0f; acc_qk[mt][nt][1] = 0.0f;
                acc_qk[mt][nt][2] = 0.0f; acc_qk[mt][nt][3] = 0.0f;
                rsum[mt][0] += v0 + v1;
                rsum[mt][1] += v2 + v3;
                const uint32_t p01 = f2h2(v0, v1);
                const uint32_t p23 = f2h2(v2, v3);
                *(uint32_t*)&g_attnh[((size_t)bh * LQ + l0 + r0) * SK + s0 + c0] = p01;
                *(uint32_t*)&g_attnh[((size_t)bh * LQ + l0 + r0 + 8) * SK + s0 + c0] = p23;
                const int gc = c0 >> 3, ch = (c0 & 7) >> 1;
                Ps32[r0 * 32       + ((gc ^ (r0 & 7)) << 2)       + ch] = p01;
                Ps32[(r0 + 8) * 32 + ((gc ^ ((r0 + 8) & 7)) << 2) + ch] = p23;
            }
        }
        __syncthreads();   // Ps ready

        // ---- P @ V^T MMA ----
#pragma unroll
        for (int ss = 0; ss < 4; ss++) {
            const uint32_t offA = (uint32_t)(((2 * ss + agh) ^ lsw) << 4);
            const uint32_t offB = (uint32_t)(((2 * ss + bgh) ^ lsw) << 4);
            uint32_t af[4][4], bf[4];
#pragma unroll
            for (int mt = 0; mt < 4; mt++)
                LDSM4(af[mt][0], af[mt][1], af[mt][2], af[mt][3],
                      aP + (uint32_t)(mt * 2048) + offA);
            LDSM4(bf[0], bf[1], bf[2], bf[3], bV + offB);
#pragma unroll
            for (int mt = 0; mt < 4; mt++) {
                MMAH(acc_pv[mt][0], af[mt], bf[0], bf[1]);
                MMAH(acc_pv[mt][1], af[mt], bf[2], bf[3]);
            }
        }
    }

    // ---- denominators ----
    __syncthreads();
    if (tid < 128) ds[tid] = 0.0f;
    __syncthreads();
#pragma unroll
    for (int mt = 0; mt < 4; mt++)
#pragma unroll
        for (int hh = 0; hh < 2; hh++) {
            float v = rsum[mt][hh];
            v += __shfl_xor_sync(0xffffffffu, v, 1);
            v += __shfl_xor_sync(0xffffffffu, v, 2);
            if ((lane & 3) == 0)
                atomicAdd(&ds[wm + mt * 16 + (lane >> 2) + hh * 8], v);
        }
    __syncthreads();

    // ---- ctx output (fp16) ----
#pragma unroll
    for (int mt = 0; mt < 4; mt++) {
        const int rl = wm + mt * 16 + (lane >> 2);
        const float inv0 = __fdividef(1.0f, ds[rl]     + 1e-4f);
        const float inv1 = __fdividef(1.0f, ds[rl + 8] + 1e-4f);
        const int l = l0 + rl;
#pragma unroll
        for (int nt = 0; nt < 2; nt++) {
            const int c = wq + nt * 8 + 2 * (lane & 3);
            *(half2*)&g_ctxh[(size_t)(l * BATCH + b) * EMB + h * HD + c] =
                __floats2half2_rn(acc_pv[mt][nt][0] * inv0, acc_pv[mt][nt][1] * inv0);
            *(half2*)&g_ctxh[(size_t)((l + 8) * BATCH + b) * EMB + h * HD + c] =
                __floats2half2_rn(acc_pv[mt][nt][2] * inv1, acc_pv[mt][nt][3] * inv1);
        }
    }
}

// =====================================================================
// avg_weights from fp16 attn: grid 4096, 256 thr
// =====================================================================
__global__ __launch_bounds__(256) void k_avg_h(float* __restrict__ outAvg)
{
    const size_t t = (size_t)blockIdx.x * 256 + threadIdx.x;
    const int s8 = (int)(t & (SK / 8 - 1));
    const int l  = (int)((t >> 8) & (LQ - 1));
    const int b  = (int)(t >> 19);
    float acc[8] = {0, 0, 0, 0, 0, 0, 0, 0};
#pragma unroll
    for (int h = 0; h < NH; h++) {
        const uint4 u = *(const uint4*)&g_attnh[((size_t)(b * NH + h) * LQ + l) * SK + s8 * 8];
        const half2* p = (const half2*)&u;
#pragma unroll
        for (int j = 0; j < 4; j++) {
            const float2 f = __half22float2(p[j]);
            acc[2 * j]     += f.x;
            acc[2 * j + 1] += f.y;
        }
    }
    float* o = outAvg + t * 8;
    const float inv = 1.0f / NH;
    *(float4*)o       = make_float4(acc[0] * inv, acc[1] * inv, acc[2] * inv, acc[3] * inv);
    *(float4*)(o + 4) = make_float4(acc[4] * inv, acc[5] * inv, acc[6] * inv, acc[7] * inv);
}

// =====================================================================
// out-projection (fp16 A from g_ctxh): grid (8, 32), 256 thr
// =====================================================================
__global__ __launch_bounds__(256, 1) void k_outproj_h(
    const float* __restrict__ Wo, const float* __restrict__ bo,
    float* __restrict__ out)
{
    const int m0 = blockIdx.y * 128, n0 = blockIdx.x * 128;

    float acc[4][4][4];
    gemm_h<true>(g_ctxh + (size_t)m0 * EMB, EMB, Wo + (size_t)n0 * EMB, EMB, EMB, acc);

    const int lane = threadIdx.x & 31, warp = threadIdx.x >> 5;
    const int wm0 = (warp >> 2) * 64, wn0 = (warp & 3) * 32;

#pragma unroll
    for (int nt = 0; nt < 4; nt++) {
        const int c = n0 + wn0 + nt * 8 + 2 * (lane & 3);
        const float b0 = bo[c], b1 = bo[c + 1];
#pragma unroll
        for (int mt = 0; mt < 4; mt++) {
            const int r = m0 + wm0 + mt * 16 + (lane >> 2);
            *(float2*)&out[(size_t)r * EMB + c] =
                make_float2(acc[mt][nt][0] + b0, acc[mt][nt][1] + b1);
            *(float2*)&out[(size_t)(r + 8) * EMB + c] =
                make_float2(acc[mt][nt][2] + b0, acc[mt][nt][3] + b1);
        }
    }
}

// =====================================================================
#define FUSED_SMEM (3072 * 16 + 512)   // 49664 bytes

extern "C" void kernel_launch(void* const* d_in, const int* in_sizes, int n_in,
                              void* d_out, int out_size)
{
    (void)in_sizes; (void)n_in; (void)out_size;
    const float* q    = (const float*)d_in[0];
    const float* k    = (const float*)d_in[1];
    const float* v    = (const float*)d_in[2];
    const float* Wqkv = (const float*)d_in[3];
    const float* bqkv = (const float*)d_in[4];
    const float* Wo   = (const float*)d_in[5];
    const float* bo   = (const float*)d_in[6];
    float* out    = (float*)d_out;
    float* outAvg = out + (size_t)LQ * BATCH * EMB;

    cudaFuncSetAttribute(k_attn_fused_h,
                         cudaFuncAttributeMaxDynamicSharedMemorySize, FUSED_SMEM);

    k_inproj_h<<<dim3(EMB / 128, MR / 128, 3), 256>>>(q, k, v, Wqkv, bqkv);
    k_attn_fused_h<<<dim3(LQ / 128, BHn), 256, FUSED_SMEM>>>();
    k_avg_h<<<4096, 256>>>(outAvg);
    k_outproj_h<<<dim3(EMB / 128, MR / 128), 256>>>(Wo, bo, out);
}

// round 6
// speedup vs baseline: 4.3917x; 1.4359x over previous
#include <cuda_runtime.h>
#include <cuda_fp16.h>
#include <math.h>
#include <stdint.h>

// Problem constants
#define LQ    2048
#define BATCH 2
#define EMB   1024
#define NH    16
#define HD    64
#define SK    2048
#define BHn   32
#define MR    4096

// ---------------- scratch (device globals) ----------------
__device__ __half g_inh[3 * MR * EMB];              // fp16 q/k/v inputs (GEMM rows)
__device__ __half g_wh[3 * EMB * EMB];              // fp16 in_proj_weight
__device__ __half g_woh[EMB * EMB];                 // fp16 out_w
__device__ __half g_qh[BHn * LQ * HD];              // [bh][l][d], pre-scaled 1/8
__device__ __half g_kh[BHn * SK * HD];              // [bh][s][d]
__device__ __half g_vth[BHn * HD * SK];             // [bh][d][s]
__device__ __half g_attnh[(size_t)BHn * LQ * SK];   // 256 MB sigmoid scores (avg only)
__device__ __half g_ctxh[MR * EMB];                 // attention out, (L,B,E) rows

// ---------------- helpers ----------------
__device__ __forceinline__ uint32_t f2h2(float a, float b) {
    half2 h = __floats2half2_rn(a, b);
    return *reinterpret_cast<uint32_t*>(&h);
}
__device__ __forceinline__ uint32_t smem_u32(const void* p) {
    return (uint32_t)__cvta_generic_to_shared(p);
}
__device__ __forceinline__ float fsigmoid(float x) {
    return __fdividef(1.0f, 1.0f + __expf(-x));
}

#define LDSM4(R0,R1,R2,R3,ADDR) \
    asm volatile("ldmatrix.sync.aligned.m8n8.x4.shared.b16 {%0,%1,%2,%3}, [%4];" \
        : "=r"(R0), "=r"(R1), "=r"(R2), "=r"(R3) : "r"(ADDR))

#define MMAH(C,A,B0,B1) \
    asm volatile("mma.sync.aligned.m16n8k16.row.col.f32.f16.f16.f32 " \
        "{%0,%1,%2,%3},{%4,%5,%6,%7},{%8,%9},{%0,%1,%2,%3};" \
        : "+f"((C)[0]), "+f"((C)[1]), "+f"((C)[2]), "+f"((C)[3]) \
        : "r"((A)[0]), "r"((A)[1]), "r"((A)[2]), "r"((A)[3]), "r"(B0), "r"(B1))

#define CPA16(DST, SRC) \
    asm volatile("cp.async.ca.shared.global [%0], [%1], 16;" \
        :: "r"(DST), "l"(SRC) : "memory")
#define CPA_COMMIT() asm volatile("cp.async.commit_group;" ::: "memory")
#define CPA_WAIT0()  asm volatile("cp.async.wait_group 0;" ::: "memory")

// =====================================================================
// fp32 -> fp16 conversion (8 elems/thread)
// =====================================================================
__global__ __launch_bounds__(256) void k_f2h(const float* __restrict__ s,
                                             __half* __restrict__ d, int n8)
{
    const int i = blockIdx.x * 256 + threadIdx.x;
    if (i < n8) {
        const float4 a = ((const float4*)s)[2 * i];
        const float4 b = ((const float4*)s)[2 * i + 1];
        uint4 o;
        o.x = f2h2(a.x, a.y); o.y = f2h2(a.z, a.w);
        o.z = f2h2(b.x, b.y); o.w = f2h2(b.z, b.w);
        ((uint4*)d)[i] = o;
    }
}

// =====================================================================
// cp.async GEMM core: CTA 128x128, 128 thr, 4 warps (2m x 2n), warp
// 64x64 (4mt x 8nt of m16n8k16), BK=64 halves, double-buffered smem.
// A: MxK fp16 row-major. B: NxK fp16 row-major (col-major operand).
// smem: A0 @0 | A1 @16K | B0 @32K | B1 @48K  (64KB total)
// =====================================================================
__device__ __forceinline__ void gemm_cp(
    const __half* __restrict__ A, int lda,
    const __half* __restrict__ B, int ldb,
    int K, float (&acc)[4][8][4], char* smem)
{
    const uint32_t sb = smem_u32(smem);
    const int tid = threadIdx.x, lane = tid & 31, warp = tid >> 5;
    const int wm0 = (warp >> 1) * 64, wn0 = (warp & 1) * 64;

    // staging: thread owns A row tid and B row tid (8 x 16B granules each)
    const int ssw = (tid & 7) << 4;
    const __half* Ap = A + (size_t)tid * lda;
    const __half* Bp = B + (size_t)tid * ldb;

    // ldmatrix addressing
    const int arow = wm0 + (lane & 15), agh = lane >> 4, lsw = lane & 7;
    const int brow = wn0 + (lane & 7) + ((lane >> 4) << 3), bgh = (lane >> 3) & 1;
    const uint32_t aB0 = sb + (uint32_t)arow * 128;
    const uint32_t bB0 = sb + 32768u + (uint32_t)brow * 128;

#pragma unroll
    for (int mt = 0; mt < 4; mt++)
#pragma unroll
        for (int nt = 0; nt < 8; nt++)
#pragma unroll
            for (int c = 0; c < 4; c++) acc[mt][nt][c] = 0.0f;

    // prologue: issue tile 0
    {
        const uint32_t ad = sb + (uint32_t)tid * 128;
        const uint32_t bd = sb + 32768u + (uint32_t)tid * 128;
#pragma unroll
        for (int g = 0; g < 8; g++) {
            CPA16(ad + (uint32_t)((g * 16) ^ ssw), Ap + g * 8);
            CPA16(bd + (uint32_t)((g * 16) ^ ssw), Bp + g * 8);
        }
        CPA_COMMIT();
    }

    const int iters = K >> 6;
    for (int it = 0; it < iters; it++) {
        CPA_WAIT0();
        __syncthreads();

        if (it + 1 < iters) {
            const __half* An = Ap + (it + 1) * 64;
            const __half* Bn = Bp + (it + 1) * 64;
            const uint32_t ad = sb + (uint32_t)(((it + 1) & 1) * 16384) + (uint32_t)tid * 128;
            const uint32_t bd = ad + 32768u;
#pragma unroll
            for (int g = 0; g < 8; g++) {
                CPA16(ad + (uint32_t)((g * 16) ^ ssw), An + g * 8);
                CPA16(bd + (uint32_t)((g * 16) ^ ssw), Bn + g * 8);
            }
            CPA_COMMIT();
        }

        const uint32_t aB = aB0 + (uint32_t)((it & 1) * 16384);
        const uint32_t bB = bB0 + (uint32_t)((it & 1) * 16384);
#pragma unroll
        for (int ss = 0; ss < 4; ss++) {
            const uint32_t offA = (uint32_t)(((2 * ss + agh) ^ lsw) << 4);
            const uint32_t offB = (uint32_t)(((2 * ss + bgh) ^ lsw) << 4);
            uint32_t af[4][4], bf[4][4];
#pragma unroll
            for (int mt = 0; mt < 4; mt++)
                LDSM4(af[mt][0], af[mt][1], af[mt][2], af[mt][3],
                      aB + (uint32_t)(mt * 2048) + offA);
#pragma unroll
            for (int bt = 0; bt < 4; bt++)
                LDSM4(bf[bt][0], bf[bt][1], bf[bt][2], bf[bt][3],
                      bB + (uint32_t)(bt * 2048) + offB);
#pragma unroll
            for (int mt = 0; mt < 4; mt++)
#pragma unroll
                for (int bt = 0; bt < 4; bt++) {
                    MMAH(acc[mt][2 * bt],     af[mt], bf[bt][0], bf[bt][1]);
                    MMAH(acc[mt][2 * bt + 1], af[mt], bf[bt][2], bf[bt][3]);
                }
        }
    }
}

#define PROJ_SMEM 65536

// =====================================================================
// in-projection: grid (8, 32, 3), 128 thr
// =====================================================================
__global__ __launch_bounds__(128, 2) void k_inproj_cp(const float* __restrict__ bias)
{
    extern __shared__ char smem[];
    const int p = blockIdx.z;
    const int m0 = blockIdx.y * 128, n0 = blockIdx.x * 128;
    const __half* A = g_inh + (size_t)p * MR * EMB + (size_t)m0 * EMB;
    const __half* B = g_wh + (size_t)p * EMB * EMB + (size_t)n0 * EMB;
    const float* bp = bias + p * EMB;
    const float scale = (p == 0) ? 0.125f : 1.0f;

    float acc[4][8][4];
    gemm_cp(A, EMB, B, EMB, EMB, acc, smem);

    const int lane = threadIdx.x & 31, warp = threadIdx.x >> 5;
    const int wm0 = (warp >> 1) * 64, wn0 = (warp & 1) * 64;

#pragma unroll
    for (int nt = 0; nt < 8; nt++) {
        const int c = n0 + wn0 + nt * 8 + 2 * (lane & 3);
        const float b0 = bp[c], b1 = bp[c + 1];
        const int h = c >> 6, d = c & 63;
#pragma unroll
        for (int mt = 0; mt < 4; mt++) {
            const int r = m0 + wm0 + mt * 16 + (lane >> 2);
#pragma unroll
            for (int half_ = 0; half_ < 2; half_++) {
                const int rr = r + half_ * 8;
                const float v0 = (acc[mt][nt][half_ * 2 + 0] + b0) * scale;
                const float v1 = (acc[mt][nt][half_ * 2 + 1] + b1) * scale;
                const int l = rr >> 1, bb = rr & 1;
                const int bh = bb * NH + h;
                if (p == 0)
                    *(half2*)&g_qh[((size_t)bh * LQ + l) * HD + d] = __floats2half2_rn(v0, v1);
                else if (p == 1)
                    *(half2*)&g_kh[((size_t)bh * SK + l) * HD + d] = __floats2half2_rn(v0, v1);
                else {
                    g_vth[((size_t)bh * HD + d)     * SK + l] = __float2half(v0);
                    g_vth[((size_t)bh * HD + d + 1) * SK + l] = __float2half(v1);
                }
            }
        }
    }
}

// =====================================================================
// out-projection: grid (8, 32), 128 thr
// =====================================================================
__global__ __launch_bounds__(128, 2) void k_outproj_cp(
    const float* __restrict__ bo, float* __restrict__ out)
{
    extern __shared__ char smem[];
    const int m0 = blockIdx.y * 128, n0 = blockIdx.x * 128;

    float acc[4][8][4];
    gemm_cp(g_ctxh + (size_t)m0 * EMB, EMB, g_woh + (size_t)n0 * EMB, EMB, EMB, acc, smem);

    const int lane = threadIdx.x & 31, warp = threadIdx.x >> 5;
    const int wm0 = (warp >> 1) * 64, wn0 = (warp & 1) * 64;

#pragma unroll
    for (int nt = 0; nt < 8; nt++) {
        const int c = n0 + wn0 + nt * 8 + 2 * (lane & 3);
        const float b0 = bo[c], b1 = bo[c + 1];
#pragma unroll
        for (int mt = 0; mt < 4; mt++) {
            const int r = m0 + wm0 + mt * 16 + (lane >> 2);
            *(float2*)&out[(size_t)r * EMB + c] =
                make_float2(acc[mt][0 + nt][0] + b0, acc[mt][nt][1] + b1);
            *(float2*)&out[(size_t)(r + 8) * EMB + c] =
                make_float2(acc[mt][nt][2] + b0, acc[mt][nt][3] + b1);
        }
    }
}

// =====================================================================
// FUSED attention: CTA = (128 l-rows, bh), 256 thr = 2 groups x 4 warps.
// Group g processes s-tiles (2*it + g)*64, it = 0..15. Per group: warp
// tiles 64x32 (2m x 2n). cp.async double-buffered K/V.
// smem: ds 512B | Q @1024 (16K) | per group @17408+g*49152:
//       K0 8K | K1 8K | V0 8K | V1 8K | P 16K
// =====================================================================
#define AT_Q     1024
#define AT_G0    17408
#define AT_GSZ   49152
#define AT_VOFF  16384
#define AT_POFF  32768
#define ATTN_SMEM (AT_G0 + 2 * AT_GSZ)   // 115712

__global__ __launch_bounds__(256, 1) void k_attn()
{
    extern __shared__ char smem[];
    const uint32_t sb = smem_u32(smem);
    float* ds = (float*)smem;

    const int bh = blockIdx.y;
    const int l0 = blockIdx.x * 128;
    const int b = bh >> 4, h = bh & 15;
    const int tid = threadIdx.x, lane = tid & 31, warp = tid >> 5;
    const int wg = warp >> 2;                 // group 0/1
    const int wl = warp & 3;
    const int wm = (wl >> 1) * 64;            // m offset within 128
    const int wq = (wl & 1) * 32;             // n offset within 64
    const uint32_t gb = AT_G0 + (uint32_t)wg * AT_GSZ;
    const int lt = tid & 127;

    if (tid < 128) ds[tid] = 0.0f;

    // ---- staging addresses ----
    // Q: 256 thr, row = tid>>1, granules (tid&1)*4..+3
    {
        const int qr = tid >> 1, qg = (tid & 1) * 4;
        const int qsw = (qr & 7) << 4;
        const __half* qs = g_qh + ((size_t)bh * LQ + l0 + qr) * HD + qg * 8;
        const uint32_t qd = sb + AT_Q + (uint32_t)qr * 128;
#pragma unroll
        for (int gi = 0; gi < 4; gi++)
            CPA16(qd + (uint32_t)((((qg + gi) * 16)) ^ qsw), qs + gi * 8);
    }
    // K/V: per group, 128 thr stage 64 rows each of K and V, 4 granules/row-half
    const int kvrow = lt >> 1, cg0 = (lt & 1) * 4;
    const int ksw = (kvrow & 7) << 4;
    const __half* kp = g_kh  + ((size_t)bh * SK + wg * 64 + kvrow) * HD + (lt & 1) * 32;
    const __half* vp = g_vth + ((size_t)bh * HD + kvrow) * SK + wg * 64 + (lt & 1) * 32;
    {
        const uint32_t kd = sb + gb + (uint32_t)kvrow * 128;
        const uint32_t vd = kd + AT_VOFF;
#pragma unroll
        for (int gi = 0; gi < 4; gi++) {
            CPA16(kd + (uint32_t)(((cg0 + gi) * 16) ^ ksw), kp + gi * 8);
            CPA16(vd + (uint32_t)(((cg0 + gi) * 16) ^ ksw), vp + gi * 8);
        }
        CPA_COMMIT();
    }

    // ---- ldmatrix addressing ----
    const int aRow = wm + (lane & 15), agh = lane >> 4, lsw = lane & 7;
    const int bRow = wq + (lane & 7) + ((lane >> 4) << 3), bgh = (lane >> 3) & 1;
    const uint32_t aQ = sb + AT_Q + (uint32_t)aRow * 128;
    const uint32_t aP = sb + gb + AT_POFF + (uint32_t)aRow * 128;
    const uint32_t bK0 = sb + gb + (uint32_t)bRow * 128;
    const uint32_t bV0 = bK0 + AT_VOFF;
    char* psm = smem + gb + AT_POFF;

    float acc_pv[4][4][4], rsum[4][2];
#pragma unroll
    for (int mt = 0; mt < 4; mt++) {
        rsum[mt][0] = rsum[mt][1] = 0.0f;
#pragma unroll
        for (int nt = 0; nt < 4; nt++)
#pragma unroll
            for (int c = 0; c < 4; c++) acc_pv[mt][nt][c] = 0.0f;
    }

    const int r0b = wm + (lane >> 2);
    const int c0b = wq + 2 * (lane & 3);

    for (int it = 0; it < 16; it++) {
        CPA_WAIT0();
        __syncthreads();

        if (it < 15) {
            kp += (size_t)128 * HD;
            vp += 128;
            const uint32_t kd = sb + gb + (uint32_t)(((it + 1) & 1) * 8192)
                              + (uint32_t)kvrow * 128;
            const uint32_t vd = kd + AT_VOFF;
#pragma unroll
            for (int gi = 0; gi < 4; gi++) {
                CPA16(kd + (uint32_t)(((cg0 + gi) * 16) ^ ksw), kp + gi * 8);
                CPA16(vd + (uint32_t)(((cg0 + gi) * 16) ^ ksw), vp + gi * 8);
            }
            CPA_COMMIT();
        }

        const uint32_t bufo = (uint32_t)((it & 1) * 8192);
        const uint32_t bK = bK0 + bufo, bV = bV0 + bufo;

        // ---- QK^T (K=64 -> 4 k16 substeps) ----
        float acc_qk[4][4][4];
#pragma unroll
        for (int mt = 0; mt < 4; mt++)
#pragma unroll
            for (int nt = 0; nt < 4; nt++)
#pragma unroll
                for (int c = 0; c < 4; c++) acc_qk[mt][nt][c] = 0.0f;

#pragma unroll
        for (int ss = 0; ss < 4; ss++) {
            const uint32_t offA = (uint32_t)(((2 * ss + agh) ^ lsw) << 4);
            const uint32_t offB = (uint32_t)(((2 * ss + bgh) ^ lsw) << 4);
            uint32_t af[4][4], bf[2][4];
#pragma unroll
            for (int mt = 0; mt < 4; mt++)
                LDSM4(af[mt][0], af[mt][1], af[mt][2], af[mt][3],
                      aQ + (uint32_t)(mt * 2048) + offA);
            LDSM4(bf[0][0], bf[0][1], bf[0][2], bf[0][3], bK + offB);
            LDSM4(bf[1][0], bf[1][1], bf[1][2], bf[1][3], bK + 2048u + offB);
#pragma unroll
            for (int mt = 0; mt < 4; mt++) {
                MMAH(acc_qk[mt][0], af[mt], bf[0][0], bf[0][1]);
                MMAH(acc_qk[mt][1], af[mt], bf[0][2], bf[0][3]);
                MMAH(acc_qk[mt][2], af[mt], bf[1][0], bf[1][1]);
                MMAH(acc_qk[mt][3], af[mt], bf[1][2], bf[1][3]);
            }
        }

        // ---- sigmoid epilogue ----
        const int s0 = (2 * it + wg) * 64;
#pragma unroll
        for (int mt = 0; mt < 4; mt++) {
            const int r0 = r0b + mt * 16;
            const int rsw = (r0 & 7);
#pragma unroll
            for (int nt = 0; nt < 4; nt++) {
                const int c0 = c0b + nt * 8;
                const float v0 = fsigmoid(acc_qk[mt][nt][0]);
                const float v1 = fsigmoid(acc_qk[mt][nt][1]);
                const float v2 = fsigmoid(acc_qk[mt][nt][2]);
                const float v3 = fsigmoid(acc_qk[mt][nt][3]);
                rsum[mt][0] += v0 + v1;
                rsum[mt][1] += v2 + v3;
                const uint32_t p01 = f2h2(v0, v1);
                const uint32_t p23 = f2h2(v2, v3);
                *(uint32_t*)&g_attnh[((size_t)bh * LQ + l0 + r0) * SK + s0 + c0] = p01;
                *(uint32_t*)&g_attnh[((size_t)bh * LQ + l0 + r0 + 8) * SK + s0 + c0] = p23;
                const int goff = (((c0 >> 3) ^ rsw) << 4) + ((c0 & 7) << 1);
                *(uint32_t*)(psm + r0 * 128 + goff) = p01;
                *(uint32_t*)(psm + (r0 + 8) * 128 + goff) = p23;
            }
        }
        __syncthreads();   // P ready (group-symmetric barrier)

        // ---- P @ V^T (K=64) ----
#pragma unroll
        for (int ss = 0; ss < 4; ss++) {
            const uint32_t offA = (uint32_t)(((2 * ss + agh) ^ lsw) << 4);
            const uint32_t offB = (uint32_t)(((2 * ss + bgh) ^ lsw) << 4);
            uint32_t af[4][4], bf[2][4];
#pragma unroll
            for (int mt = 0; mt < 4; mt++)
                LDSM4(af[mt][0], af[mt][1], af[mt][2], af[mt][3],
                      aP + (uint32_t)(mt * 2048) + offA);
            LDSM4(bf[0][0], bf[0][1], bf[0][2], bf[0][3], bV + offB);
            LDSM4(bf[1][0], bf[1][1], bf[1][2], bf[1][3], bV + 2048u + offB);
#pragma unroll
            for (int mt = 0; mt < 4; mt++) {
                MMAH(acc_pv[mt][0], af[mt], bf[0][0], bf[0][1]);
                MMAH(acc_pv[mt][1], af[mt], bf[0][2], bf[0][3]);
                MMAH(acc_pv[mt][2], af[mt], bf[1][0], bf[1][1]);
                MMAH(acc_pv[mt][3], af[mt], bf[1][2], bf[1][3]);
            }
        }
    }

    // ---- denominators: quad shuffle + atomic into ds (both groups) ----
    __syncthreads();
#pragma unroll
    for (int mt = 0; mt < 4; mt++)
#pragma unroll
        for (int hh = 0; hh < 2; hh++) {
            float v = rsum[mt][hh];
            v += __shfl_xor_sync(0xffffffffu, v, 1);
            v += __shfl_xor_sync(0xffffffffu, v, 2);
            if ((lane & 3) == 0)
                atomicAdd(&ds[wm + mt * 16 + (lane >> 2) + hh * 8], v);
        }
    __syncthreads();

    // ---- cross-group PV reduction via padded smem ----
    float* scr = (float*)(smem + AT_G0 + AT_GSZ);   // group-1 block, 128x65 floats
    if (tid >= 128) {
        const int t = tid - 128;
#pragma unroll
        for (int mt = 0; mt < 4; mt++)
#pragma unroll
            for (int nt = 0; nt < 4; nt++)
#pragma unroll
                for (int c = 0; c < 4; c++)
                    scr[t * 65 + (mt * 4 + nt) * 4 + c] = acc_pv[mt][nt][c];
    }
    __syncthreads();
    if (tid < 128) {
#pragma unroll
        for (int mt = 0; mt < 4; mt++) {
            const int rl = wm + mt * 16 + (lane >> 2);
            const float inv0 = __fdividef(1.0f, ds[rl]     + 1e-4f);
            const float inv1 = __fdividef(1.0f, ds[rl + 8] + 1e-4f);
            const int l = l0 + rl;
#pragma unroll
            for (int nt = 0; nt < 4; nt++) {
                const int c = wq + nt * 8 + 2 * (lane & 3);
                const int si = tid * 65 + (mt * 4 + nt) * 4;
                const float o0 = (acc_pv[mt][nt][0] + scr[si + 0]) * inv0;
                const float o1 = (acc_pv[mt][nt][1] + scr[si + 1]) * inv0;
                const float o2 = (acc_pv[mt][nt][2] + scr[si + 2]) * inv1;
                const float o3 = (acc_pv[mt][nt][3] + scr[si + 3]) * inv1;
                *(half2*)&g_ctxh[(size_t)(l * BATCH + b) * EMB + h * HD + c] =
                    __floats2half2_rn(o0, o1);
                *(half2*)&g_ctxh[(size_t)((l + 8) * BATCH + b) * EMB + h * HD + c] =
                    __floats2half2_rn(o2, o3);
            }
        }
    }
}

// =====================================================================
// avg_weights from fp16 attn: grid 4096, 256 thr
// =====================================================================
__global__ __launch_bounds__(256) void k_avg_h(float* __restrict__ outAvg)
{
    const size_t t = (size_t)blockIdx.x * 256 + threadIdx.x;
    const int s8 = (int)(t & (SK / 8 - 1));
    const int l  = (int)((t >> 8) & (LQ - 1));
    const int b  = (int)(t >> 19);
    float acc[8] = {0, 0, 0, 0, 0, 0, 0, 0};
#pragma unroll
    for (int h = 0; h < NH; h++) {
        const uint4 u = *(const uint4*)&g_attnh[((size_t)(b * NH + h) * LQ + l) * SK + s8 * 8];
        const half2* p = (const half2*)&u;
#pragma unroll
        for (int j = 0; j < 4; j++) {
            const float2 f = __half22float2(p[j]);
            acc[2 * j]     += f.x;
            acc[2 * j + 1] += f.y;
        }
    }
    float* o = outAvg + t * 8;
    const float inv = 1.0f / NH;
    *(float4*)o       = make_float4(acc[0] * inv, acc[1] * inv, acc[2] * inv, acc[3] * inv);
    *(float4*)(o + 4) = make_float4(acc[4] * inv, acc[5] * inv, acc[6] * inv, acc[7] * inv);
}

// =====================================================================
extern "C" void kernel_launch(void* const* d_in, const int* in_sizes, int n_in,
                              void* d_out, int out_size)
{
    (void)in_sizes; (void)n_in; (void)out_size;
    const float* q    = (const float*)d_in[0];
    const float* k    = (const float*)d_in[1];
    const float* v    = (const float*)d_in[2];
    const float* Wqkv = (const float*)d_in[3];
    const float* bqkv = (const float*)d_in[4];
    const float* Wo   = (const float*)d_in[5];
    const float* bo   = (const float*)d_in[6];
    float* out    = (float*)d_out;
    float* outAvg = out + (size_t)LQ * BATCH * EMB;

    cudaFuncSetAttribute(k_inproj_cp,  cudaFuncAttributeMaxDynamicSharedMemorySize, PROJ_SMEM);
    cudaFuncSetAttribute(k_outproj_cp, cudaFuncAttributeMaxDynamicSharedMemorySize, PROJ_SMEM);
    cudaFuncSetAttribute(k_attn,       cudaFuncAttributeMaxDynamicSharedMemorySize, ATTN_SMEM);

    __half* inh; __half* wh; __half* woh;
    cudaGetSymbolAddress((void**)&inh, g_inh);
    cudaGetSymbolAddress((void**)&wh,  g_wh);
    cudaGetSymbolAddress((void**)&woh, g_woh);

    const int nIn = MR * EMB / 8;          // 524288
    const int nW  = 3 * EMB * EMB / 8;     // 393216
    const int nWo = EMB * EMB / 8;         // 131072
    k_f2h<<<(nIn + 255) / 256, 256>>>(q, inh, nIn);
    k_f2h<<<(nIn + 255) / 256, 256>>>(k, inh + (size_t)MR * EMB, nIn);
    k_f2h<<<(nIn + 255) / 256, 256>>>(v, inh + (size_t)2 * MR * EMB, nIn);
    k_f2h<<<(nW + 255) / 256, 256>>>(Wqkv, wh, nW);
    k_f2h<<<(nWo + 255) / 256, 256>>>(Wo, woh, nWo);

    k_inproj_cp<<<dim3(EMB / 128, MR / 128, 3), 128, PROJ_SMEM>>>(bqkv);
    k_attn<<<dim3(LQ / 128, BHn), 256, ATTN_SMEM>>>();
    k_avg_h<<<4096, 256>>>(outAvg);
    k_outproj_cp<<<dim3(EMB / 128, MR / 128), 128, PROJ_SMEM>>>(bo, out);
}

// round 7
// speedup vs baseline: 4.5381x; 1.0333x over previous
#include <cuda_runtime.h>
#include <cuda_fp16.h>
#include <math.h>
#include <stdint.h>

// Problem constants
#define LQ    2048
#define BATCH 2
#define EMB   1024
#define NH    16
#define HD    64
#define SK    2048
#define BHn   32
#define MR    4096

// ---------------- scratch (device globals) ----------------
__device__ __half g_inh[3 * MR * EMB];              // fp16 q/k/v inputs (GEMM rows)
__device__ __half g_wh[3 * EMB * EMB];              // fp16 in_proj_weight
__device__ __half g_woh[EMB * EMB];                 // fp16 out_w
__device__ __half g_qh[BHn * LQ * HD];              // [bh][l][d], pre-scaled 1/8
__device__ __half g_kh[BHn * SK * HD];              // [bh][s][d]
__device__ __half g_vth[BHn * HD * SK];             // [bh][d][s]
__device__ __half g_attnh[(size_t)BHn * LQ * SK];   // 256 MB fp16 scores (avg only)
__device__ __half g_ctxh[MR * EMB];                 // attention out, (L,B,E) rows

// ---------------- helpers ----------------
__device__ __forceinline__ uint32_t f2h2(float a, float b) {
    half2 h = __floats2half2_rn(a, b);
    return *reinterpret_cast<uint32_t*>(&h);
}
__device__ __forceinline__ uint32_t smem_u32(const void* p) {
    return (uint32_t)__cvta_generic_to_shared(p);
}
__device__ __forceinline__ float fsigmoid(float x) {
    return __fdividef(1.0f, 1.0f + __expf(-x));
}

#define LDSM4(R0,R1,R2,R3,ADDR) \
    asm volatile("ldmatrix.sync.aligned.m8n8.x4.shared.b16 {%0,%1,%2,%3}, [%4];" \
        : "=r"(R0), "=r"(R1), "=r"(R2), "=r"(R3) : "r"(ADDR))

#define MMAH(C,A,B0,B1) \
    asm volatile("mma.sync.aligned.m16n8k16.row.col.f32.f16.f16.f32 " \
        "{%0,%1,%2,%3},{%4,%5,%6,%7},{%8,%9},{%0,%1,%2,%3};" \
        : "+f"((C)[0]), "+f"((C)[1]), "+f"((C)[2]), "+f"((C)[3]) \
        : "r"((A)[0]), "r"((A)[1]), "r"((A)[2]), "r"((A)[3]), "r"(B0), "r"(B1))

#define CPA16(DST, SRC) \
    asm volatile("cp.async.ca.shared.global [%0], [%1], 16;" \
        :: "r"(DST), "l"(SRC) : "memory")
#define CPA_COMMIT() asm volatile("cp.async.commit_group;" ::: "memory")
#define CPA_WAIT0()  asm volatile("cp.async.wait_group 0;" ::: "memory")

// named barrier: 128 threads of one group
#define BARG(ID) asm volatile("bar.sync %0, 128;" :: "r"(ID) : "memory")

// =====================================================================
// fp32 -> fp16 conversion: 3 sources in one launch (grid.y selects)
// =====================================================================
__global__ __launch_bounds__(256) void k_f2h3(
    const float* __restrict__ s0, const float* __restrict__ s1,
    const float* __restrict__ s2, __half* __restrict__ d, int n8)
{
    const float* s = (blockIdx.y == 0) ? s0 : (blockIdx.y == 1) ? s1 : s2;
    __half* dp = d + (size_t)blockIdx.y * n8 * 8;
    const int i = blockIdx.x * 256 + threadIdx.x;
    if (i < n8) {
        const float4 a = ((const float4*)s)[2 * i];
        const float4 b = ((const float4*)s)[2 * i + 1];
        uint4 o;
        o.x = f2h2(a.x, a.y); o.y = f2h2(a.z, a.w);
        o.z = f2h2(b.x, b.y); o.w = f2h2(b.z, b.w);
        ((uint4*)dp)[i] = o;
    }
}

__global__ __launch_bounds__(256) void k_f2h(const float* __restrict__ s,
                                             __half* __restrict__ d, int n8)
{
    const int i = blockIdx.x * 256 + threadIdx.x;
    if (i < n8) {
        const float4 a = ((const float4*)s)[2 * i];
        const float4 b = ((const float4*)s)[2 * i + 1];
        uint4 o;
        o.x = f2h2(a.x, a.y); o.y = f2h2(a.z, a.w);
        o.z = f2h2(b.x, b.y); o.w = f2h2(b.z, b.w);
        ((uint4*)d)[i] = o;
    }
}

// =====================================================================
// cp.async GEMM core: CTA 128x128, 128 thr, 4 warps (2x2), warp 64x64,
// BK=64 halves, double-buffered. smem: A0|A1|B0|B1 (64KB)
// =====================================================================
__device__ __forceinline__ void gemm_cp(
    const __half* __restrict__ A, int lda,
    const __half* __restrict__ B, int ldb,
    int K, float (&acc)[4][8][4], char* smem)
{
    const uint32_t sb = smem_u32(smem);
    const int tid = threadIdx.x, lane = tid & 31, warp = tid >> 5;
    const int wm0 = (warp >> 1) * 64, wn0 = (warp & 1) * 64;

    const int ssw = (tid & 7) << 4;
    const __half* Ap = A + (size_t)tid * lda;
    const __half* Bp = B + (size_t)tid * ldb;

    const int arow = wm0 + (lane & 15), agh = lane >> 4, lsw = lane & 7;
    const int brow = wn0 + (lane & 7) + ((lane >> 4) << 3), bgh = (lane >> 3) & 1;
    const uint32_t aB0 = sb + (uint32_t)arow * 128;
    const uint32_t bB0 = sb + 32768u + (uint32_t)brow * 128;

#pragma unroll
    for (int mt = 0; mt < 4; mt++)
#pragma unroll
        for (int nt = 0; nt < 8; nt++)
#pragma unroll
            for (int c = 0; c < 4; c++) acc[mt][nt][c] = 0.0f;

    {
        const uint32_t ad = sb + (uint32_t)tid * 128;
        const uint32_t bd = sb + 32768u + (uint32_t)tid * 128;
#pragma unroll
        for (int g = 0; g < 8; g++) {
            CPA16(ad + (uint32_t)((g * 16) ^ ssw), Ap + g * 8);
            CPA16(bd + (uint32_t)((g * 16) ^ ssw), Bp + g * 8);
        }
        CPA_COMMIT();
    }

    const int iters = K >> 6;
    for (int it = 0; it < iters; it++) {
        CPA_WAIT0();
        __syncthreads();

        if (it + 1 < iters) {
            const __half* An = Ap + (it + 1) * 64;
            const __half* Bn = Bp + (it + 1) * 64;
            const uint32_t ad = sb + (uint32_t)(((it + 1) & 1) * 16384) + (uint32_t)tid * 128;
            const uint32_t bd = ad + 32768u;
#pragma unroll
            for (int g = 0; g < 8; g++) {
                CPA16(ad + (uint32_t)((g * 16) ^ ssw), An + g * 8);
                CPA16(bd + (uint32_t)((g * 16) ^ ssw), Bn + g * 8);
            }
            CPA_COMMIT();
        }

        const uint32_t aB = aB0 + (uint32_t)((it & 1) * 16384);
        const uint32_t bB = bB0 + (uint32_t)((it & 1) * 16384);
#pragma unroll
        for (int ss = 0; ss < 4; ss++) {
            const uint32_t offA = (uint32_t)(((2 * ss + agh) ^ lsw) << 4);
            const uint32_t offB = (uint32_t)(((2 * ss + bgh) ^ lsw) << 4);
            uint32_t af[4][4], bf[4][4];
#pragma unroll
            for (int mt = 0; mt < 4; mt++)
                LDSM4(af[mt][0], af[mt][1], af[mt][2], af[mt][3],
                      aB + (uint32_t)(mt * 2048) + offA);
#pragma unroll
            for (int bt = 0; bt < 4; bt++)
                LDSM4(bf[bt][0], bf[bt][1], bf[bt][2], bf[bt][3],
                      bB + (uint32_t)(bt * 2048) + offB);
#pragma unroll
            for (int mt = 0; mt < 4; mt++)
#pragma unroll
                for (int bt = 0; bt < 4; bt++) {
                    MMAH(acc[mt][2 * bt],     af[mt], bf[bt][0], bf[bt][1]);
                    MMAH(acc[mt][2 * bt + 1], af[mt], bf[bt][2], bf[bt][3]);
                }
        }
    }
}

#define PROJ_SMEM 65536

// =====================================================================
// in-projection: grid (8, 32, 3), 128 thr
// =====================================================================
__global__ __launch_bounds__(128, 2) void k_inproj_cp(const float* __restrict__ bias)
{
    extern __shared__ char smem[];
    const int p = blockIdx.z;
    const int m0 = blockIdx.y * 128, n0 = blockIdx.x * 128;
    const __half* A = g_inh + (size_t)p * MR * EMB + (size_t)m0 * EMB;
    const __half* B = g_wh + (size_t)p * EMB * EMB + (size_t)n0 * EMB;
    const float* bp = bias + p * EMB;
    const float scale = (p == 0) ? 0.125f : 1.0f;

    float acc[4][8][4];
    gemm_cp(A, EMB, B, EMB, EMB, acc, smem);

    const int lane = threadIdx.x & 31, warp = threadIdx.x >> 5;
    const int wm0 = (warp >> 1) * 64, wn0 = (warp & 1) * 64;

#pragma unroll
    for (int nt = 0; nt < 8; nt++) {
        const int c = n0 + wn0 + nt * 8 + 2 * (lane & 3);
        const float b0 = bp[c], b1 = bp[c + 1];
        const int h = c >> 6, d = c & 63;
#pragma unroll
        for (int mt = 0; mt < 4; mt++) {
            const int r = m0 + wm0 + mt * 16 + (lane >> 2);
#pragma unroll
            for (int half_ = 0; half_ < 2; half_++) {
                const int rr = r + half_ * 8;
                const float v0 = (acc[mt][nt][half_ * 2 + 0] + b0) * scale;
                const float v1 = (acc[mt][nt][half_ * 2 + 1] + b1) * scale;
                const int l = rr >> 1, bb = rr & 1;
                const int bh = bb * NH + h;
                if (p == 0)
                    *(half2*)&g_qh[((size_t)bh * LQ + l) * HD + d] = __floats2half2_rn(v0, v1);
                else if (p == 1)
                    *(half2*)&g_kh[((size_t)bh * SK + l) * HD + d] = __floats2half2_rn(v0, v1);
                else {
                    g_vth[((size_t)bh * HD + d)     * SK + l] = __float2half(v0);
                    g_vth[((size_t)bh * HD + d + 1) * SK + l] = __float2half(v1);
                }
            }
        }
    }
}

// =====================================================================
// out-projection: grid (8, 32), 128 thr
// =====================================================================
__global__ __launch_bounds__(128, 2) void k_outproj_cp(
    const float* __restrict__ bo, float* __restrict__ out)
{
    extern __shared__ char smem[];
    const int m0 = blockIdx.y * 128, n0 = blockIdx.x * 128;

    float acc[4][8][4];
    gemm_cp(g_ctxh + (size_t)m0 * EMB, EMB, g_woh + (size_t)n0 * EMB, EMB, EMB, acc, smem);

    const int lane = threadIdx.x & 31, warp = threadIdx.x >> 5;
    const int wm0 = (warp >> 1) * 64, wn0 = (warp & 1) * 64;

#pragma unroll
    for (int nt = 0; nt < 8; nt++) {
        const int c = n0 + wn0 + nt * 8 + 2 * (lane & 3);
        const float b0 = bo[c], b1 = bo[c + 1];
#pragma unroll
        for (int mt = 0; mt < 4; mt++) {
            const int r = m0 + wm0 + mt * 16 + (lane >> 2);
            *(float2*)&out[(size_t)r * EMB + c] =
                make_float2(acc[mt][nt][0] + b0, acc[mt][nt][1] + b1);
            *(float2*)&out[(size_t)(r + 8) * EMB + c] =
                make_float2(acc[mt][nt][2] + b0, acc[mt][nt][3] + b1);
        }
    }
}

// =====================================================================
// FUSED attention: CTA = (128 l-rows, bh), 256 thr = 2 groups x 4 warps.
// Group g handles s-tiles (2*it + g)*64. In-loop sync = NAMED barriers
// (per group), so the groups drift and one group's MUFU/staging hides
// under the other's HMMA (groups share SMSPs pairwise: wid%4).
// smem: ds 512B | Q @1024 (16K) | per group @17408+g*49152:
//       K0 8K | K1 8K | V0 8K | V1 8K | P 16K
// =====================================================================
#define AT_Q     1024
#define AT_G0    17408
#define AT_GSZ   49152
#define AT_VOFF  16384
#define AT_POFF  32768
#define ATTN_SMEM (AT_G0 + 2 * AT_GSZ)   // 115712

__global__ __launch_bounds__(256, 1) void k_attn()
{
    extern __shared__ char smem[];
    const uint32_t sb = smem_u32(smem);
    float* ds = (float*)smem;

    const int bh = blockIdx.y;
    const int l0 = blockIdx.x * 128;
    const int b = bh >> 4, h = bh & 15;
    const int tid = threadIdx.x, lane = tid & 31, warp = tid >> 5;
    const int wg = warp >> 2;                 // group 0/1
    const int wl = warp & 3;
    const int wm = (wl >> 1) * 64;
    const int wq = (wl & 1) * 32;
    const uint32_t gb = AT_G0 + (uint32_t)wg * AT_GSZ;
    const int lt = tid & 127;
    const int barid = 1 + wg;

    if (tid < 128) ds[tid] = 0.0f;

    // ---- Q staging (cp.async, all 256 threads) ----
    {
        const int qr = tid >> 1, qg = (tid & 1) * 4;
        const int qsw = (qr & 7) << 4;
        const __half* qs = g_qh + ((size_t)bh * LQ + l0 + qr) * HD + qg * 8;
        const uint32_t qd = sb + AT_Q + (uint32_t)qr * 128;
#pragma unroll
        for (int gi = 0; gi < 4; gi++)
            CPA16(qd + (uint32_t)((((qg + gi) * 16)) ^ qsw), qs + gi * 8);
    }
    // K/V staging addresses (per group)
    const int kvrow = lt >> 1, cg0 = (lt & 1) * 4;
    const int ksw = (kvrow & 7) << 4;
    const __half* kp = g_kh  + ((size_t)bh * SK + wg * 64 + kvrow) * HD + (lt & 1) * 32;
    const __half* vp = g_vth + ((size_t)bh * HD + kvrow) * SK + wg * 64 + (lt & 1) * 32;
    {
        const uint32_t kd = sb + gb + (uint32_t)kvrow * 128;
        const uint32_t vd = kd + AT_VOFF;
#pragma unroll
        for (int gi = 0; gi < 4; gi++) {
            CPA16(kd + (uint32_t)(((cg0 + gi) * 16) ^ ksw), kp + gi * 8);
            CPA16(vd + (uint32_t)(((cg0 + gi) * 16) ^ ksw), vp + gi * 8);
        }
        CPA_COMMIT();
    }

    // ---- ldmatrix addressing ----
    const int aRow = wm + (lane & 15), agh = lane >> 4, lsw = lane & 7;
    const int bRow = wq + (lane & 7) + ((lane >> 4) << 3), bgh = (lane >> 3) & 1;
    const uint32_t aQ = sb + AT_Q + (uint32_t)aRow * 128;
    const uint32_t aP = sb + gb + AT_POFF + (uint32_t)aRow * 128;
    const uint32_t bK0 = sb + gb + (uint32_t)bRow * 128;
    const uint32_t bV0 = bK0 + AT_VOFF;
    char* psm = smem + gb + AT_POFF;

    float acc_pv[4][4][4], rsum[4][2];
#pragma unroll
    for (int mt = 0; mt < 4; mt++) {
        rsum[mt][0] = rsum[mt][1] = 0.0f;
#pragma unroll
        for (int nt = 0; nt < 4; nt++)
#pragma unroll
            for (int c = 0; c < 4; c++) acc_pv[mt][nt][c] = 0.0f;
    }

    const int r0b = wm + (lane >> 2);
    const int c0b = wq + 2 * (lane & 3);

    for (int it = 0; it < 16; it++) {
        CPA_WAIT0();
        if (it == 0) __syncthreads();   // Q visibility across groups
        else BARG(barid);

        if (it < 15) {
            kp += (size_t)128 * HD;
            vp += 128;
            const uint32_t kd = sb + gb + (uint32_t)(((it + 1) & 1) * 8192)
                              + (uint32_t)kvrow * 128;
            const uint32_t vd = kd + AT_VOFF;
#pragma unroll
            for (int gi = 0; gi < 4; gi++) {
                CPA16(kd + (uint32_t)(((cg0 + gi) * 16) ^ ksw), kp + gi * 8);
                CPA16(vd + (uint32_t)(((cg0 + gi) * 16) ^ ksw), vp + gi * 8);
            }
            CPA_COMMIT();
        }

        const uint32_t bufo = (uint32_t)((it & 1) * 8192);
        const uint32_t bK = bK0 + bufo, bV = bV0 + bufo;

        // ---- QK^T (K=64) ----
        float acc_qk[4][4][4];
#pragma unroll
        for (int mt = 0; mt < 4; mt++)
#pragma unroll
            for (int nt = 0; nt < 4; nt++)
#pragma unroll
                for (int c = 0; c < 4; c++) acc_qk[mt][nt][c] = 0.0f;

#pragma unroll
        for (int ss = 0; ss < 4; ss++) {
            const uint32_t offA = (uint32_t)(((2 * ss + agh) ^ lsw) << 4);
            const uint32_t offB = (uint32_t)(((2 * ss + bgh) ^ lsw) << 4);
            uint32_t af[4][4], bf[2][4];
#pragma unroll
            for (int mt = 0; mt < 4; mt++)
                LDSM4(af[mt][0], af[mt][1], af[mt][2], af[mt][3],
                      aQ + (uint32_t)(mt * 2048) + offA);
            LDSM4(bf[0][0], bf[0][1], bf[0][2], bf[0][3], bK + offB);
            LDSM4(bf[1][0], bf[1][1], bf[1][2], bf[1][3], bK + 2048u + offB);
#pragma unroll
            for (int mt = 0; mt < 4; mt++) {
                MMAH(acc_qk[mt][0], af[mt], bf[0][0], bf[0][1]);
                MMAH(acc_qk[mt][1], af[mt], bf[0][2], bf[0][3]);
                MMAH(acc_qk[mt][2], af[mt], bf[1][0], bf[1][1]);
                MMAH(acc_qk[mt][3], af[mt], bf[1][2], bf[1][3]);
            }
        }

        // ---- sigmoid epilogue: P smem + fp16 attn store + rowsums ----
        const int s0 = (2 * it + wg) * 64;
#pragma unroll
        for (int mt = 0; mt < 4; mt++) {
            const int r0 = r0b + mt * 16;
            const int rsw = (r0 & 7);
#pragma unroll
            for (int nt = 0; nt < 4; nt++) {
                const int c0 = c0b + nt * 8;
                const float v0 = fsigmoid(acc_qk[mt][nt][0]);
                const float v1 = fsigmoid(acc_qk[mt][nt][1]);
                const float v2 = fsigmoid(acc_qk[mt][nt][2]);
                const float v3 = fsigmoid(acc_qk[mt][nt][3]);
                rsum[mt][0] += v0 + v1;
                rsum[mt][1] += v2 + v3;
                const uint32_t p01 = f2h2(v0, v1);
                const uint32_t p23 = f2h2(v2, v3);
                const int goff = (((c0 >> 3) ^ rsw) << 4) + ((c0 & 7) << 1);
                *(uint32_t*)(psm + r0 * 128 + goff) = p01;
                *(uint32_t*)(psm + (r0 + 8) * 128 + goff) = p23;
                *(uint32_t*)&g_attnh[((size_t)bh * LQ + l0 + r0) * SK + s0 + c0] = p01;
                *(uint32_t*)&g_attnh[((size_t)bh * LQ + l0 + r0 + 8) * SK + s0 + c0] = p23;
            }
        }
        BARG(barid);   // P ready (group-local)

        // ---- P @ V^T (K=64) ----
#pragma unroll
        for (int ss = 0; ss < 4; ss++) {
            const uint32_t offA = (uint32_t)(((2 * ss + agh) ^ lsw) << 4);
            const uint32_t offB = (uint32_t)(((2 * ss + bgh) ^ lsw) << 4);
            uint32_t af[4][4], bf[2][4];
#pragma unroll
            for (int mt = 0; mt < 4; mt++)
                LDSM4(af[mt][0], af[mt][1], af[mt][2], af[mt][3],
                      aP + (uint32_t)(mt * 2048) + offA);
            LDSM4(bf[0][0], bf[0][1], bf[0][2], bf[0][3], bV + offB);
            LDSM4(bf[1][0], bf[1][1], bf[1][2], bf[1][3], bV + 2048u + offB);
#pragma unroll
            for (int mt = 0; mt < 4; mt++) {
                MMAH(acc_pv[mt][0], af[mt], bf[0][0], bf[0][1]);
                MMAH(acc_pv[mt][1], af[mt], bf[0][2], bf[0][3]);
                MMAH(acc_pv[mt][2], af[mt], bf[1][0], bf[1][1]);
                MMAH(acc_pv[mt][3], af[mt], bf[1][2], bf[1][3]);
            }
        }
    }

    // ---- denominators: quad shuffle + atomic into ds (both groups) ----
    __syncthreads();
#pragma unroll
    for (int mt = 0; mt < 4; mt++)
#pragma unroll
        for (int hh = 0; hh < 2; hh++) {
            float v = rsum[mt][hh];
            v += __shfl_xor_sync(0xffffffffu, v, 1);
            v += __shfl_xor_sync(0xffffffffu, v, 2);
            if ((lane & 3) == 0)
                atomicAdd(&ds[wm + mt * 16 + (lane >> 2) + hh * 8], v);
        }
    __syncthreads();

    // ---- cross-group PV reduction via padded smem ----
    float* scr = (float*)(smem + AT_G0 + AT_GSZ);   // 128 x 65 floats
    if (tid >= 128) {
        const int t = tid - 128;
#pragma unroll
        for (int mt = 0; mt < 4; mt++)
#pragma unroll
            for (int nt = 0; nt < 4; nt++)
#pragma unroll
                for (int c = 0; c < 4; c++)
                    scr[t * 65 + (mt * 4 + nt) * 4 + c] = acc_pv[mt][nt][c];
    }
    __syncthreads();
    if (tid < 128) {
#pragma unroll
        for (int mt = 0; mt < 4; mt++) {
            const int rl = wm + mt * 16 + (lane >> 2);
            const float inv0 = __fdividef(1.0f, ds[rl]     + 1e-4f);
            const float inv1 = __fdividef(1.0f, ds[rl + 8] + 1e-4f);
            const int l = l0 + rl;
#pragma unroll
            for (int nt = 0; nt < 4; nt++) {
                const int c = wq + nt * 8 + 2 * (lane & 3);
                const int si = tid * 65 + (mt * 4 + nt) * 4;
                const float o0 = (acc_pv[mt][nt][0] + scr[si + 0]) * inv0;
                const float o1 = (acc_pv[mt][nt][1] + scr[si + 1]) * inv0;
                const float o2 = (acc_pv[mt][nt][2] + scr[si + 2]) * inv1;
                const float o3 = (acc_pv[mt][nt][3] + scr[si + 3]) * inv1;
                *(half2*)&g_ctxh[(size_t)(l * BATCH + b) * EMB + h * HD + c] =
                    __floats2half2_rn(o0, o1);
                *(half2*)&g_ctxh[(size_t)((l + 8) * BATCH + b) * EMB + h * HD + c] =
                    __floats2half2_rn(o2, o3);
            }
        }
    }
}

// =====================================================================
// avg_weights from fp16 attn: grid 4096, 256 thr
// =====================================================================
__global__ __launch_bounds__(256) void k_avg_h(float* __restrict__ outAvg)
{
    const size_t t = (size_t)blockIdx.x * 256 + threadIdx.x;
    const int s8 = (int)(t & (SK / 8 - 1));
    const int l  = (int)((t >> 8) & (LQ - 1));
    const int b  = (int)(t >> 19);
    float acc[8] = {0, 0, 0, 0, 0, 0, 0, 0};
#pragma unroll
    for (int h = 0; h < NH; h++) {
        const uint4 u = *(const uint4*)&g_attnh[((size_t)(b * NH + h) * LQ + l) * SK + s8 * 8];
        const half2* p = (const half2*)&u;
#pragma unroll
        for (int j = 0; j < 4; j++) {
            const float2 f = __half22float2(p[j]);
            acc[2 * j]     += f.x;
            acc[2 * j + 1] += f.y;
        }
    }
    float* o = outAvg + t * 8;
    const float inv = 1.0f / NH;
    *(float4*)o       = make_float4(acc[0] * inv, acc[1] * inv, acc[2] * inv, acc[3] * inv);
    *(float4*)(o + 4) = make_float4(acc[4] * inv, acc[5] * inv, acc[6] * inv, acc[7] * inv);
}

// =====================================================================
extern "C" void kernel_launch(void* const* d_in, const int* in_sizes, int n_in,
                              void* d_out, int out_size)
{
    (void)in_sizes; (void)n_in; (void)out_size;
    const float* q    = (const float*)d_in[0];
    const float* k    = (const float*)d_in[1];
    const float* v    = (const float*)d_in[2];
    const float* Wqkv = (const float*)d_in[3];
    const float* bqkv = (const float*)d_in[4];
    const float* Wo   = (const float*)d_in[5];
    const float* bo   = (const float*)d_in[6];
    float* out    = (float*)d_out;
    float* outAvg = out + (size_t)LQ * BATCH * EMB;

    cudaFuncSetAttribute(k_inproj_cp,  cudaFuncAttributeMaxDynamicSharedMemorySize, PROJ_SMEM);
    cudaFuncSetAttribute(k_outproj_cp, cudaFuncAttributeMaxDynamicSharedMemorySize, PROJ_SMEM);
    cudaFuncSetAttribute(k_attn,       cudaFuncAttributeMaxDynamicSharedMemorySize, ATTN_SMEM);

    __half* inh; __half* wh; __half* woh;
    cudaGetSymbolAddress((void**)&inh, g_inh);
    cudaGetSymbolAddress((void**)&wh,  g_wh);
    cudaGetSymbolAddress((void**)&woh, g_woh);

    const int nIn = MR * EMB / 8;          // 524288
    const int nW  = 3 * EMB * EMB / 8;     // 393216
    const int nWo = EMB * EMB / 8;         // 131072
    k_f2h3<<<dim3((nIn + 255) / 256, 3), 256>>>(q, k, v, inh, nIn);
    k_f2h<<<(nW + 255) / 256, 256>>>(Wqkv, wh, nW);
    k_f2h<<<(nWo + 255) / 256, 256>>>(Wo, woh, nWo);

    k_inproj_cp<<<dim3(EMB / 128, MR / 128, 3), 128, PROJ_SMEM>>>(bqkv);
    k_attn<<<dim3(LQ / 128, BHn), 256, ATTN_SMEM>>>();
    k_avg_h<<<4096, 256>>>(outAvg);
    k_outproj_cp<<<dim3(EMB / 128, MR / 128), 128, PROJ_SMEM>>>(bo, out);
}

// round 8
// speedup vs baseline: 4.6613x; 1.0272x over previous
#include <cuda_runtime.h>
#include <cuda_fp16.h>
#include <math.h>
#include <stdint.h>

// Problem constants
#define LQ    2048
#define BATCH 2
#define EMB   1024
#define NH    16
#define HD    64
#define SK    2048
#define BHn   32
#define MR    4096

// ---------------- scratch (device globals) ----------------
__device__ __half g_inh[3 * MR * EMB];              // fp16 q/k/v inputs (GEMM rows)
__device__ __half g_wh[3 * EMB * EMB];              // fp16 in_proj_weight
__device__ __half g_woh[EMB * EMB];                 // fp16 out_w
__device__ __half g_qh[BHn * LQ * HD];              // [bh][l][d], pre-scaled 1/16
__device__ __half g_kh[BHn * SK * HD];              // [bh][s][d]
__device__ __half g_vth[BHn * HD * SK];             // [bh][d][s]
__device__ __half g_attnh[(size_t)BHn * LQ * SK];   // 256 MB fp16 scores (avg only)
__device__ __half g_ctxh[MR * EMB];                 // attention out, (L,B,E) rows

// ---------------- helpers ----------------
__device__ __forceinline__ uint32_t f2h2(float a, float b) {
    half2 h = __floats2half2_rn(a, b);
    return *reinterpret_cast<uint32_t*>(&h);
}
__device__ __forceinline__ uint32_t smem_u32(const void* p) {
    return (uint32_t)__cvta_generic_to_shared(p);
}

#define LDSM4(R0,R1,R2,R3,ADDR) \
    asm volatile("ldmatrix.sync.aligned.m8n8.x4.shared.b16 {%0,%1,%2,%3}, [%4];" \
        : "=r"(R0), "=r"(R1), "=r"(R2), "=r"(R3) : "r"(ADDR))

#define MMAH(C,A,B0,B1) \
    asm volatile("mma.sync.aligned.m16n8k16.row.col.f32.f16.f16.f32 " \
        "{%0,%1,%2,%3},{%4,%5,%6,%7},{%8,%9},{%0,%1,%2,%3};" \
        : "+f"((C)[0]), "+f"((C)[1]), "+f"((C)[2]), "+f"((C)[3]) \
        : "r"((A)[0]), "r"((A)[1]), "r"((A)[2]), "r"((A)[3]), "r"(B0), "r"(B1))

#define CPA16(DST, SRC) \
    asm volatile("cp.async.ca.shared.global [%0], [%1], 16;" \
        :: "r"(DST), "l"(SRC) : "memory")
#define CPA_COMMIT() asm volatile("cp.async.commit_group;" ::: "memory")
#define CPA_WAIT0()  asm volatile("cp.async.wait_group 0;" ::: "memory")

// named barrier: 128 threads of one group
#define BARG(ID) asm volatile("bar.sync %0, 128;" :: "r"(ID) : "memory")

// sigmoid(2u) for a packed half2 u: 0.5*tanh(u) + 0.5  (Q pre-scaled by extra 0.5)
__device__ __forceinline__ uint32_t sig_h2(float a, float b) {
    uint32_t p = f2h2(a, b);
    asm("tanh.approx.f16x2 %0, %0;" : "+r"(p));
    const half2 H05 = __half2half2(__ushort_as_half(0x3800));
    half2 t = *reinterpret_cast<half2*>(&p);
    t = __hfma2(t, H05, H05);
    return *reinterpret_cast<uint32_t*>(&t);
}

// =====================================================================
// fp32 -> fp16 conversion: 3 sources in one launch (grid.y selects)
// =====================================================================
__global__ __launch_bounds__(256) void k_f2h3(
    const float* __restrict__ s0, const float* __restrict__ s1,
    const float* __restrict__ s2, __half* __restrict__ d, int n8)
{
    const float* s = (blockIdx.y == 0) ? s0 : (blockIdx.y == 1) ? s1 : s2;
    __half* dp = d + (size_t)blockIdx.y * n8 * 8;
    const int i = blockIdx.x * 256 + threadIdx.x;
    if (i < n8) {
        const float4 a = ((const float4*)s)[2 * i];
        const float4 b = ((const float4*)s)[2 * i + 1];
        uint4 o;
        o.x = f2h2(a.x, a.y); o.y = f2h2(a.z, a.w);
        o.z = f2h2(b.x, b.y); o.w = f2h2(b.z, b.w);
        ((uint4*)dp)[i] = o;
    }
}

__global__ __launch_bounds__(256) void k_f2h(const float* __restrict__ s,
                                             __half* __restrict__ d, int n8)
{
    const int i = blockIdx.x * 256 + threadIdx.x;
    if (i < n8) {
        const float4 a = ((const float4*)s)[2 * i];
        const float4 b = ((const float4*)s)[2 * i + 1];
        uint4 o;
        o.x = f2h2(a.x, a.y); o.y = f2h2(a.z, a.w);
        o.z = f2h2(b.x, b.y); o.w = f2h2(b.z, b.w);
        ((uint4*)d)[i] = o;
    }
}

// =====================================================================
// cp.async GEMM core: CTA 128x128, 128 thr, 4 warps (2x2), warp 64x64,
// BK=64 halves, double-buffered. smem: A0|A1|B0|B1 (64KB)
// =====================================================================
__device__ __forceinline__ void gemm_cp(
    const __half* __restrict__ A, int lda,
    const __half* __restrict__ B, int ldb,
    int K, float (&acc)[4][8][4], char* smem)
{
    const uint32_t sb = smem_u32(smem);
    const int tid = threadIdx.x, lane = tid & 31, warp = tid >> 5;
    const int wm0 = (warp >> 1) * 64, wn0 = (warp & 1) * 64;

    const int ssw = (tid & 7) << 4;
    const __half* Ap = A + (size_t)tid * lda;
    const __half* Bp = B + (size_t)tid * ldb;

    const int arow = wm0 + (lane & 15), agh = lane >> 4, lsw = lane & 7;
    const int brow = wn0 + (lane & 7) + ((lane >> 4) << 3), bgh = (lane >> 3) & 1;
    const uint32_t aB0 = sb + (uint32_t)arow * 128;
    const uint32_t bB0 = sb + 32768u + (uint32_t)brow * 128;

#pragma unroll
    for (int mt = 0; mt < 4; mt++)
#pragma unroll
        for (int nt = 0; nt < 8; nt++)
#pragma unroll
            for (int c = 0; c < 4; c++) acc[mt][nt][c] = 0.0f;

    {
        const uint32_t ad = sb + (uint32_t)tid * 128;
        const uint32_t bd = sb + 32768u + (uint32_t)tid * 128;
#pragma unroll
        for (int g = 0; g < 8; g++) {
            CPA16(ad + (uint32_t)((g * 16) ^ ssw), Ap + g * 8);
            CPA16(bd + (uint32_t)((g * 16) ^ ssw), Bp + g * 8);
        }
        CPA_COMMIT();
    }

    const int iters = K >> 6;
    for (int it = 0; it < iters; it++) {
        CPA_WAIT0();
        __syncthreads();

        if (it + 1 < iters) {
            const __half* An = Ap + (it + 1) * 64;
            const __half* Bn = Bp + (it + 1) * 64;
            const uint32_t ad = sb + (uint32_t)(((it + 1) & 1) * 16384) + (uint32_t)tid * 128;
            const uint32_t bd = ad + 32768u;
#pragma unroll
            for (int g = 0; g < 8; g++) {
                CPA16(ad + (uint32_t)((g * 16) ^ ssw), An + g * 8);
                CPA16(bd + (uint32_t)((g * 16) ^ ssw), Bn + g * 8);
            }
            CPA_COMMIT();
        }

        const uint32_t aB = aB0 + (uint32_t)((it & 1) * 16384);
        const uint32_t bB = bB0 + (uint32_t)((it & 1) * 16384);
#pragma unroll
        for (int ss = 0; ss < 4; ss++) {
            const uint32_t offA = (uint32_t)(((2 * ss + agh) ^ lsw) << 4);
            const uint32_t offB = (uint32_t)(((2 * ss + bgh) ^ lsw) << 4);
            uint32_t af[4][4], bf[4][4];
#pragma unroll
            for (int mt = 0; mt < 4; mt++)
                LDSM4(af[mt][0], af[mt][1], af[mt][2], af[mt][3],
                      aB + (uint32_t)(mt * 2048) + offA);
#pragma unroll
            for (int bt = 0; bt < 4; bt++)
                LDSM4(bf[bt][0], bf[bt][1], bf[bt][2], bf[bt][3],
                      bB + (uint32_t)(bt * 2048) + offB);
#pragma unroll
            for (int mt = 0; mt < 4; mt++)
#pragma unroll
                for (int bt = 0; bt < 4; bt++) {
                    MMAH(acc[mt][2 * bt],     af[mt], bf[bt][0], bf[bt][1]);
                    MMAH(acc[mt][2 * bt + 1], af[mt], bf[bt][2], bf[bt][3]);
                }
        }
    }
}

#define PROJ_SMEM 65536

// =====================================================================
// in-projection: grid (8, 32, 3), 128 thr.  Q scaled by 1/16 (extra 0.5
// folded in for the tanh-based sigmoid).
// =====================================================================
__global__ __launch_bounds__(128, 2) void k_inproj_cp(const float* __restrict__ bias)
{
    extern __shared__ char smem[];
    const int p = blockIdx.z;
    const int m0 = blockIdx.y * 128, n0 = blockIdx.x * 128;
    const __half* A = g_inh + (size_t)p * MR * EMB + (size_t)m0 * EMB;
    const __half* B = g_wh + (size_t)p * EMB * EMB + (size_t)n0 * EMB;
    const float* bp = bias + p * EMB;
    const float scale = (p == 0) ? 0.0625f : 1.0f;

    float acc[4][8][4];
    gemm_cp(A, EMB, B, EMB, EMB, acc, smem);

    const int lane = threadIdx.x & 31, warp = threadIdx.x >> 5;
    const int wm0 = (warp >> 1) * 64, wn0 = (warp & 1) * 64;

#pragma unroll
    for (int nt = 0; nt < 8; nt++) {
        const int c = n0 + wn0 + nt * 8 + 2 * (lane & 3);
        const float b0 = bp[c], b1 = bp[c + 1];
        const int h = c >> 6, d = c & 63;
#pragma unroll
        for (int mt = 0; mt < 4; mt++) {
            const int r = m0 + wm0 + mt * 16 + (lane >> 2);
#pragma unroll
            for (int half_ = 0; half_ < 2; half_++) {
                const int rr = r + half_ * 8;
                const float v0 = (acc[mt][nt][half_ * 2 + 0] + b0) * scale;
                const float v1 = (acc[mt][nt][half_ * 2 + 1] + b1) * scale;
                const int l = rr >> 1, bb = rr & 1;
                const int bh = bb * NH + h;
                if (p == 0)
                    *(half2*)&g_qh[((size_t)bh * LQ + l) * HD + d] = __floats2half2_rn(v0, v1);
                else if (p == 1)
                    *(half2*)&g_kh[((size_t)bh * SK + l) * HD + d] = __floats2half2_rn(v0, v1);
                else {
                    g_vth[((size_t)bh * HD + d)     * SK + l] = __float2half(v0);
                    g_vth[((size_t)bh * HD + d + 1) * SK + l] = __float2half(v1);
                }
            }
        }
    }
}

// =====================================================================
// out-projection: grid (8, 32), 128 thr
// =====================================================================
__global__ __launch_bounds__(128, 2) void k_outproj_cp(
    const float* __restrict__ bo, float* __restrict__ out)
{
    extern __shared__ char smem[];
    const int m0 = blockIdx.y * 128, n0 = blockIdx.x * 128;

    float acc[4][8][4];
    gemm_cp(g_ctxh + (size_t)m0 * EMB, EMB, g_woh + (size_t)n0 * EMB, EMB, EMB, acc, smem);

    const int lane = threadIdx.x & 31, warp = threadIdx.x >> 5;
    const int wm0 = (warp >> 1) * 64, wn0 = (warp & 1) * 64;

#pragma unroll
    for (int nt = 0; nt < 8; nt++) {
        const int c = n0 + wn0 + nt * 8 + 2 * (lane & 3);
        const float b0 = bo[c], b1 = bo[c + 1];
#pragma unroll
        for (int mt = 0; mt < 4; mt++) {
            const int r = m0 + wm0 + mt * 16 + (lane >> 2);
            *(float2*)&out[(size_t)r * EMB + c] =
                make_float2(acc[mt][nt][0] + b0, acc[mt][nt][1] + b1);
            *(float2*)&out[(size_t)(r + 8) * EMB + c] =
                make_float2(acc[mt][nt][2] + b0, acc[mt][nt][3] + b1);
        }
    }
}

// =====================================================================
// FUSED attention: CTA = (128 l-rows, bh), 256 thr = 2 groups x 4 warps.
// tanh.approx.f16x2 sigmoid; denominators via P@ones MMA (no scalar
// reduction). Named per-group barriers let the groups drift.
// smem: Q @1024 (16K) | per group @17408+g*49152: K0|K1|V0|V1|P
// =====================================================================
#define AT_Q     1024
#define AT_G0    17408
#define AT_GSZ   49152
#define AT_VOFF  16384
#define AT_POFF  32768
#define ATTN_SMEM (AT_G0 + 2 * AT_GSZ)   // 115712

__global__ __launch_bounds__(256, 1) void k_attn()
{
    extern __shared__ char smem[];
    const uint32_t sb = smem_u32(smem);

    const int bh = blockIdx.y;
    const int l0 = blockIdx.x * 128;
    const int b = bh >> 4, h = bh & 15;
    const int tid = threadIdx.x, lane = tid & 31, warp = tid >> 5;
    const int wg = warp >> 2;
    const int wl = warp & 3;
    const int wm = (wl >> 1) * 64;
    const int wq = (wl & 1) * 32;
    const uint32_t gb = AT_G0 + (uint32_t)wg * AT_GSZ;
    const int lt = tid & 127;
    const int barid = 1 + wg;
    const uint32_t ONES = 0x3C003C00u;   // half2(1,1)

    // ---- Q staging ----
    {
        const int qr = tid >> 1, qg = (tid & 1) * 4;
        const int qsw = (qr & 7) << 4;
        const __half* qs = g_qh + ((size_t)bh * LQ + l0 + qr) * HD + qg * 8;
        const uint32_t qd = sb + AT_Q + (uint32_t)qr * 128;
#pragma unroll
        for (int gi = 0; gi < 4; gi++)
            CPA16(qd + (uint32_t)((((qg + gi) * 16)) ^ qsw), qs + gi * 8);
    }
    // K/V staging
    const int kvrow = lt >> 1, cg0 = (lt & 1) * 4;
    const int ksw = (kvrow & 7) << 4;
    const __half* kp = g_kh  + ((size_t)bh * SK + wg * 64 + kvrow) * HD + (lt & 1) * 32;
    const __half* vp = g_vth + ((size_t)bh * HD + kvrow) * SK + wg * 64 + (lt & 1) * 32;
    {
        const uint32_t kd = sb + gb + (uint32_t)kvrow * 128;
        const uint32_t vd = kd + AT_VOFF;
#pragma unroll
        for (int gi = 0; gi < 4; gi++) {
            CPA16(kd + (uint32_t)(((cg0 + gi) * 16) ^ ksw), kp + gi * 8);
            CPA16(vd + (uint32_t)(((cg0 + gi) * 16) ^ ksw), vp + gi * 8);
        }
        CPA_COMMIT();
    }

    // ---- ldmatrix addressing ----
    const int aRow = wm + (lane & 15), agh = lane >> 4, lsw = lane & 7;
    const int bRow = wq + (lane & 7) + ((lane >> 4) << 3), bgh = (lane >> 3) & 1;
    const uint32_t aQ = sb + AT_Q + (uint32_t)aRow * 128;
    const uint32_t aP = sb + gb + AT_POFF + (uint32_t)aRow * 128;
    const uint32_t bK0 = sb + gb + (uint32_t)bRow * 128;
    const uint32_t bV0 = bK0 + AT_VOFF;
    char* psm = smem + gb + AT_POFF;

    float acc_pv[4][4][4], acc_den[4][4];
#pragma unroll
    for (int mt = 0; mt < 4; mt++) {
#pragma unroll
        for (int c = 0; c < 4; c++) acc_den[mt][c] = 0.0f;
#pragma unroll
        for (int nt = 0; nt < 4; nt++)
#pragma unroll
            for (int c = 0; c < 4; c++) acc_pv[mt][nt][c] = 0.0f;
    }

    const int r0b = wm + (lane >> 2);
    const int c0b = wq + 2 * (lane & 3);

    for (int it = 0; it < 16; it++) {
        CPA_WAIT0();
        if (it == 0) __syncthreads();
        else BARG(barid);

        if (it < 15) {
            kp += (size_t)128 * HD;
            vp += 128;
            const uint32_t kd = sb + gb + (uint32_t)(((it + 1) & 1) * 8192)
                              + (uint32_t)kvrow * 128;
            const uint32_t vd = kd + AT_VOFF;
#pragma unroll
            for (int gi = 0; gi < 4; gi++) {
                CPA16(kd + (uint32_t)(((cg0 + gi) * 16) ^ ksw), kp + gi * 8);
                CPA16(vd + (uint32_t)(((cg0 + gi) * 16) ^ ksw), vp + gi * 8);
            }
            CPA_COMMIT();
        }

        const uint32_t bufo = (uint32_t)((it & 1) * 8192);
        const uint32_t bK = bK0 + bufo, bV = bV0 + bufo;

        // ---- QK^T (K=64) ----
        float acc_qk[4][4][4];
#pragma unroll
        for (int mt = 0; mt < 4; mt++)
#pragma unroll
            for (int nt = 0; nt < 4; nt++)
#pragma unroll
                for (int c = 0; c < 4; c++) acc_qk[mt][nt][c] = 0.0f;

#pragma unroll
        for (int ss = 0; ss < 4; ss++) {
            const uint32_t offA = (uint32_t)(((2 * ss + agh) ^ lsw) << 4);
            const uint32_t offB = (uint32_t)(((2 * ss + bgh) ^ lsw) << 4);
            uint32_t af[4][4], bf[2][4];
#pragma unroll
            for (int mt = 0; mt < 4; mt++)
                LDSM4(af[mt][0], af[mt][1], af[mt][2], af[mt][3],
                      aQ + (uint32_t)(mt * 2048) + offA);
            LDSM4(bf[0][0], bf[0][1], bf[0][2], bf[0][3], bK + offB);
            LDSM4(bf[1][0], bf[1][1], bf[1][2], bf[1][3], bK + 2048u + offB);
#pragma unroll
            for (int mt = 0; mt < 4; mt++) {
                MMAH(acc_qk[mt][0], af[mt], bf[0][0], bf[0][1]);
                MMAH(acc_qk[mt][1], af[mt], bf[0][2], bf[0][3]);
                MMAH(acc_qk[mt][2], af[mt], bf[1][0], bf[1][1]);
                MMAH(acc_qk[mt][3], af[mt], bf[1][2], bf[1][3]);
            }
        }

        // ---- sigmoid epilogue (tanh.approx.f16x2) ----
        const int s0 = (2 * it + wg) * 64;
#pragma unroll
        for (int mt = 0; mt < 4; mt++) {
            const int r0 = r0b + mt * 16;
            const int rsw = (r0 & 7);
#pragma unroll
            for (int nt = 0; nt < 4; nt++) {
                const int c0 = c0b + nt * 8;
                const uint32_t p01 = sig_h2(acc_qk[mt][nt][0], acc_qk[mt][nt][1]);
                const uint32_t p23 = sig_h2(acc_qk[mt][nt][2], acc_qk[mt][nt][3]);
                const int goff = (((c0 >> 3) ^ rsw) << 4) + ((c0 & 7) << 1);
                *(uint32_t*)(psm + r0 * 128 + goff) = p01;
                *(uint32_t*)(psm + (r0 + 8) * 128 + goff) = p23;
                *(uint32_t*)&g_attnh[((size_t)bh * LQ + l0 + r0) * SK + s0 + c0] = p01;
                *(uint32_t*)&g_attnh[((size_t)bh * LQ + l0 + r0 + 8) * SK + s0 + c0] = p23;
            }
        }
        BARG(barid);   // P ready (group-local)

        // ---- P @ V^T (K=64) + P @ ones (denominators) ----
#pragma unroll
        for (int ss = 0; ss < 4; ss++) {
            const uint32_t offA = (uint32_t)(((2 * ss + agh) ^ lsw) << 4);
            const uint32_t offB = (uint32_t)(((2 * ss + bgh) ^ lsw) << 4);
            uint32_t af[4][4], bf[2][4];
#pragma unroll
            for (int mt = 0; mt < 4; mt++)
                LDSM4(af[mt][0], af[mt][1], af[mt][2], af[mt][3],
                      aP + (uint32_t)(mt * 2048) + offA);
            LDSM4(bf[0][0], bf[0][1], bf[0][2], bf[0][3], bV + offB);
            LDSM4(bf[1][0], bf[1][1], bf[1][2], bf[1][3], bV + 2048u + offB);
#pragma unroll
            for (int mt = 0; mt < 4; mt++) {
                MMAH(acc_pv[mt][0], af[mt], bf[0][0], bf[0][1]);
                MMAH(acc_pv[mt][1], af[mt], bf[0][2], bf[0][3]);
                MMAH(acc_pv[mt][2], af[mt], bf[1][0], bf[1][1]);
                MMAH(acc_pv[mt][3], af[mt], bf[1][2], bf[1][3]);
                MMAH(acc_den[mt],   af[mt], ONES, ONES);
            }
        }
    }

    // ---- cross-group merge: PV + den via padded smem ----
    __syncthreads();   // both groups fully done (group-1 region reused)
    float* scr = (float*)(smem + AT_G0 + AT_GSZ);   // 128 x 73 floats
    if (tid >= 128) {
        const int t = tid - 128;
#pragma unroll
        for (int mt = 0; mt < 4; mt++) {
#pragma unroll
            for (int nt = 0; nt < 4; nt++)
#pragma unroll
                for (int c = 0; c < 4; c++)
                    scr[t * 73 + (mt * 4 + nt) * 4 + c] = acc_pv[mt][nt][c];
            scr[t * 73 + 64 + mt * 2]     = acc_den[mt][0];
            scr[t * 73 + 64 + mt * 2 + 1] = acc_den[mt][2];
        }
    }
    __syncthreads();
    if (tid < 128) {
#pragma unroll
        for (int mt = 0; mt < 4; mt++) {
            const int rl = wm + mt * 16 + (lane >> 2);
            const float den0 = acc_den[mt][0] + scr[tid * 73 + 64 + mt * 2];
            const float den1 = acc_den[mt][2] + scr[tid * 73 + 64 + mt * 2 + 1];
            const float inv0 = __fdividef(1.0f, den0 + 1e-4f);
            const float inv1 = __fdividef(1.0f, den1 + 1e-4f);
            const int l = l0 + rl;
#pragma unroll
            for (int nt = 0; nt < 4; nt++) {
                const int c = wq + nt * 8 + 2 * (lane & 3);
                const int si = tid * 73 + (mt * 4 + nt) * 4;
                const float o0 = (acc_pv[mt][nt][0] + scr[si + 0]) * inv0;
                const float o1 = (acc_pv[mt][nt][1] + scr[si + 1]) * inv0;
                const float o2 = (acc_pv[mt][nt][2] + scr[si + 2]) * inv1;
                const float o3 = (acc_pv[mt][nt][3] + scr[si + 3]) * inv1;
                *(half2*)&g_ctxh[(size_t)(l * BATCH + b) * EMB + h * HD + c] =
                    __floats2half2_rn(o0, o1);
                *(half2*)&g_ctxh[(size_t)((l + 8) * BATCH + b) * EMB + h * HD + c] =
                    __floats2half2_rn(o2, o3);
            }
        }
    }
}

// =====================================================================
// avg_weights from fp16 attn: grid 4096, 256 thr
// =====================================================================
__global__ __launch_bounds__(256) void k_avg_h(float* __restrict__ outAvg)
{
    const size_t t = (size_t)blockIdx.x * 256 + threadIdx.x;
    const int s8 = (int)(t & (SK / 8 - 1));
    const int l  = (int)((t >> 8) & (LQ - 1));
    const int b  = (int)(t >> 19);
    float acc[8] = {0, 0, 0, 0, 0, 0, 0, 0};
#pragma unroll
    for (int h = 0; h < NH; h++) {
        const uint4 u = *(const uint4*)&g_attnh[((size_t)(b * NH + h) * LQ + l) * SK + s8 * 8];
        const half2* p = (const half2*)&u;
#pragma unroll
        for (int j = 0; j < 4; j++) {
            const float2 f = __half22float2(p[j]);
            acc[2 * j]     += f.x;
            acc[2 * j + 1] += f.y;
        }
    }
    float* o = outAvg + t * 8;
    const float inv = 1.0f / NH;
    *(float4*)o       = make_float4(acc[0] * inv, acc[1] * inv, acc[2] * inv, acc[3] * inv);
    *(float4*)(o + 4) = make_float4(acc[4] * inv, acc[5] * inv, acc[6] * inv, acc[7] * inv);
}

// =====================================================================
extern "C" void kernel_launch(void* const* d_in, const int* in_sizes, int n_in,
                              void* d_out, int out_size)
{
    (void)in_sizes; (void)n_in; (void)out_size;
    const float* q    = (const float*)d_in[0];
    const float* k    = (const float*)d_in[1];
    const float* v    = (const float*)d_in[2];
    const float* Wqkv = (const float*)d_in[3];
    const float* bqkv = (const float*)d_in[4];
    const float* Wo   = (const float*)d_in[5];
    const float* bo   = (const float*)d_in[6];
    float* out    = (float*)d_out;
    float* outAvg = out + (size_t)LQ * BATCH * EMB;

    cudaFuncSetAttribute(k_inproj_cp,  cudaFuncAttributeMaxDynamicSharedMemorySize, PROJ_SMEM);
    cudaFuncSetAttribute(k_outproj_cp, cudaFuncAttributeMaxDynamicSharedMemorySize, PROJ_SMEM);
    cudaFuncSetAttribute(k_attn,       cudaFuncAttributeMaxDynamicSharedMemorySize, ATTN_SMEM);

    __half* inh; __half* wh; __half* woh;
    cudaGetSymbolAddress((void**)&inh, g_inh);
    cudaGetSymbolAddress((void**)&wh,  g_wh);
    cudaGetSymbolAddress((void**)&woh, g_woh);

    const int nIn = MR * EMB / 8;          // 524288
    const int nW  = 3 * EMB * EMB / 8;     // 393216
    const int nWo = EMB * EMB / 8;         // 131072
    k_f2h3<<<dim3((nIn + 255) / 256, 3), 256>>>(q, k, v, inh, nIn);
    k_f2h<<<(nW + 255) / 256, 256>>>(Wqkv, wh, nW);
    k_f2h<<<(nWo + 255) / 256, 256>>>(Wo, woh, nWo);

    k_inproj_cp<<<dim3(EMB / 128, MR / 128, 3), 128, PROJ_SMEM>>>(bqkv);
    k_attn<<<dim3(LQ / 128, BHn), 256, ATTN_SMEM>>>();
    k_avg_h<<<4096, 256>>>(outAvg);
    k_outproj_cp<<<dim3(EMB / 128, MR / 128), 128, PROJ_SMEM>>>(bo, out);
}